// round 14
// baseline (speedup 1.0000x reference)
#include <cuda_runtime.h>
#include <cuda_bf16.h>
#include <math.h>
#include <stdint.h>

#define BATCH 2
#define SEQ 4096
#define DM 1024
#define SD 16
#define M_ROWS (BATCH*SEQ)   // 8192
#define NB1 1152             // GEMM1 N (1024 delta + 16 B + 16 C + 96 pad)
#define NCH 16
#define CHL (SEQ/NCH)        // 256
#define LOG2E 1.4426950408889634f

// ---------------- scratch (device globals) -----------------------------------
__device__ float g_delta[(size_t)M_ROWS * DM];
__device__ float g_Bsel [(size_t)M_ROWS * SD];
__device__ float g_Csel [(size_t)M_ROWS * SD];
__device__ float g_ssm  [(size_t)M_ROWS * DM];
__device__ float g_hfinal[BATCH * DM];
__device__ float g_hproj [BATCH * DM];
__device__ float g_raw  [M_ROWS];
__device__ float g_hchunk[(size_t)BATCH * NCH * DM * SD];
__device__ float g_sumdel[(size_t)BATCH * NCH * DM];
__device__ __nv_bfloat16 g_xh[(size_t)M_ROWS * DM];
__device__ __nv_bfloat16 g_xl[(size_t)M_ROWS * DM];
__device__ __nv_bfloat16 g_sh[(size_t)M_ROWS * DM];
__device__ __nv_bfloat16 g_sl[(size_t)M_ROWS * DM];
__device__ __nv_bfloat16 g_w1[(size_t)2 * DM * NB1];     // [k<1024 hi][k+1024 lo]
__device__ __nv_bfloat16 g_w2[(size_t)2 * DM * DM];      // W_ctx hi/lo

// ---------------- PTX helpers ------------------------------------------------
__device__ __forceinline__ void ldsm_x4(uint32_t r[4], uint32_t addr) {
    asm volatile("ldmatrix.sync.aligned.m8n8.x4.shared.b16 {%0,%1,%2,%3}, [%4];\n"
        : "=r"(r[0]), "=r"(r[1]), "=r"(r[2]), "=r"(r[3]) : "r"(addr));
}
__device__ __forceinline__ void ldsm_x4_t(uint32_t r[4], uint32_t addr) {
    asm volatile("ldmatrix.sync.aligned.m8n8.x4.trans.shared.b16 {%0,%1,%2,%3}, [%4];\n"
        : "=r"(r[0]), "=r"(r[1]), "=r"(r[2]), "=r"(r[3]) : "r"(addr));
}
__device__ __forceinline__ void mma_bf16(float c[4], const uint32_t a[4],
                                         uint32_t b0, uint32_t b1) {
    asm volatile("mma.sync.aligned.m16n8k16.row.col.f32.bf16.bf16.f32 "
        "{%0,%1,%2,%3}, {%4,%5,%6,%7}, {%8,%9}, {%0,%1,%2,%3};\n"
        : "+f"(c[0]), "+f"(c[1]), "+f"(c[2]), "+f"(c[3])
        : "r"(a[0]), "r"(a[1]), "r"(a[2]), "r"(a[3]), "r"(b0), "r"(b1));
}
__device__ __forceinline__ void cp16(uint32_t saddr, const void* gaddr) {
    asm volatile("cp.async.cg.shared.global [%0], [%1], 16;\n" :: "r"(saddr), "l"(gaddr));
}

// ---------------- GEMM smem layout (3-stage, 256x128 block) ---------------------
#define ASTG 20480                   // 256*40*2
#define BSTG 8704                    // 32*136*2
#define STGB (2*ASTG + 2*BSTG)       // 58368 per stage
#define GSMEM (3*STGB)               // 175104

// ---------------- dual-split bf16 HMMA GEMM ------------------------------------
// Block 256x128, 8 warps (4x2), warp tile 64x64. 3 passes: AhBh + AhBl + AlBh.
template<int MODE>
__global__ void __launch_bounds__(256, 1) hmma_gemm(
    const __nv_bfloat16* __restrict__ Ahg, const __nv_bfloat16* __restrict__ Alg,
    const __nv_bfloat16* __restrict__ Bhg, const __nv_bfloat16* __restrict__ Blg,
    float* __restrict__ C, const float* __restrict__ scale_ptr, int N)
{
    extern __shared__ char smem[];
    uint32_t sb = (uint32_t)__cvta_generic_to_shared(smem);

    const int tid  = threadIdx.x;
    const int warp = tid >> 5, lane = tid & 31;
    const int wm = warp >> 1, wn = warp & 1;          // 4 x 2 warp grid
    const int brow = blockIdx.y * 256, bcol = blockIdx.x * 128;

    float acc[4][8][4];
#pragma unroll
    for (int i = 0; i < 4; i++)
#pragma unroll
        for (int j = 0; j < 8; j++)
#pragma unroll
            for (int c = 0; c < 4; c++) acc[i][j][c] = 0.f;

    const __nv_bfloat16* Ah = Ahg + (size_t)brow * DM;
    const __nv_bfloat16* Al = Alg + (size_t)brow * DM;
    const __nv_bfloat16* Bh = Bhg + bcol;
    const __nv_bfloat16* Bl = Blg + bcol;

    const uint32_t a_base = (uint32_t)(((wm * 64 + (lane & 15)) * 40 + (lane >> 4) * 8) * 2);
    const uint32_t b_base = (uint32_t)(((lane & 15) * 136 + wn * 64 + (lane >> 4) * 8) * 2);

    auto load_stage = [&](int s, int k0) {
        uint32_t base = sb + (uint32_t)(s * STGB);
#pragma unroll
        for (int i = 0; i < 4; i++) {              // A tiles: 256 x 32
            int idx = tid + i * 256;               // 0..1023
            int r = idx >> 2, c = (idx & 3) * 8;
            uint32_t so = (uint32_t)((r * 40 + c) * 2);
            const size_t go = (size_t)r * DM + k0 + c;
            cp16(base + so,        Ah + go);
            cp16(base + ASTG + so, Al + go);
        }
#pragma unroll
        for (int i = 0; i < 2; i++) {              // B tiles: 32 x 128
            int idx = tid + i * 256;               // 0..511
            int r = idx >> 4, c = (idx & 15) * 8;
            uint32_t so = (uint32_t)((r * 136 + c) * 2);
            const size_t go = (size_t)(k0 + r) * N + c;
            cp16(base + 2 * ASTG + so,        Bh + go);
            cp16(base + 2 * ASTG + BSTG + so, Bl + go);
        }
    };

    load_stage(0, 0);
    asm volatile("cp.async.commit_group;\n");
    load_stage(1, 32);
    asm volatile("cp.async.commit_group;\n");

    const int NK = DM / 32;   // 32
    int s = 0;
    for (int kt = 0; kt < NK; kt++) {
        asm volatile("cp.async.wait_group 1;\n");
        __syncthreads();
        if (kt + 2 < NK) {
            int s2 = s + 2; if (s2 >= 3) s2 -= 3;
            load_stage(s2, (kt + 2) * 32);
        }
        asm volatile("cp.async.commit_group;\n");

        uint32_t stg = sb + (uint32_t)(s * STGB);
        uint32_t sAh = stg + a_base;
        uint32_t sAl = stg + ASTG + a_base;
        uint32_t sBh = stg + 2 * ASTG + b_base;
        uint32_t sBl = stg + 2 * ASTG + BSTG + b_base;
#pragma unroll
        for (int kk = 0; kk < 2; kk++) {
            const uint32_t ao = kk * 32;       // +16 cols * 2B
            const uint32_t bo = kk * 4352;     // +16 rows * 136 * 2B

            uint32_t ah[4][4];
#pragma unroll
            for (int mt = 0; mt < 4; mt++)
                ldsm_x4(ah[mt], sAh + ao + (uint32_t)(mt * 1280));
            uint32_t bh_[4][4];
#pragma unroll
            for (int np = 0; np < 4; np++)
                ldsm_x4_t(bh_[np], sBh + bo + (uint32_t)(np * 32));

#pragma unroll
            for (int mt = 0; mt < 4; mt++)
#pragma unroll
                for (int nt = 0; nt < 8; nt++)
                    mma_bf16(acc[mt][nt], ah[mt],
                             bh_[nt >> 1][(nt & 1) * 2], bh_[nt >> 1][(nt & 1) * 2 + 1]);

            {   // Ah x Bl
                uint32_t bl_[4][4];
#pragma unroll
                for (int np = 0; np < 4; np++)
                    ldsm_x4_t(bl_[np], sBl + bo + (uint32_t)(np * 32));
#pragma unroll
                for (int mt = 0; mt < 4; mt++)
#pragma unroll
                    for (int nt = 0; nt < 8; nt++)
                        mma_bf16(acc[mt][nt], ah[mt],
                                 bl_[nt >> 1][(nt & 1) * 2], bl_[nt >> 1][(nt & 1) * 2 + 1]);
            }
            {   // Al x Bh
                uint32_t al[4][4];
#pragma unroll
                for (int mt = 0; mt < 4; mt++)
                    ldsm_x4(al[mt], sAl + ao + (uint32_t)(mt * 1280));
#pragma unroll
                for (int mt = 0; mt < 4; mt++)
#pragma unroll
                    for (int nt = 0; nt < 8; nt++)
                        mma_bf16(acc[mt][nt], al[mt],
                                 bh_[nt >> 1][(nt & 1) * 2], bh_[nt >> 1][(nt & 1) * 2 + 1]);
            }
        }
        if (++s >= 3) s -= 3;
    }

    float scl = 1.0f;
    if (MODE == 0 && scale_ptr) scl = *scale_ptr;
    const int g = lane >> 2, tg = lane & 3;
#pragma unroll
    for (int mt = 0; mt < 4; mt++) {
#pragma unroll
        for (int nt = 0; nt < 8; nt++) {
            int col = bcol + wn * 64 + nt * 8 + tg * 2;
#pragma unroll
            for (int half = 0; half < 2; half++) {
                int row = brow + wm * 64 + mt * 16 + g + half * 8;
                float v0 = acc[mt][nt][half * 2], v1 = acc[mt][nt][half * 2 + 1];
                if (MODE == 0) {
                    *(float2*)&C[(size_t)row * DM + col] = make_float2(v0 * scl, v1 * scl);
                } else {
                    if (col < DM) {
                        v0 = fmaxf(v0, 0.f) + log1pf(__expf(-fabsf(v0)));
                        v1 = fmaxf(v1, 0.f) + log1pf(__expf(-fabsf(v1)));
                        *(float2*)&g_delta[(size_t)row * DM + col] = make_float2(v0, v1);
                    } else if (col < DM + SD) {
                        *(float2*)&g_Bsel[(size_t)row * SD + col - DM] = make_float2(v0, v1);
                    } else if (col < DM + 2 * SD) {
                        *(float2*)&g_Csel[(size_t)row * SD + col - DM - SD] = make_float2(v0, v1);
                    }
                }
            }
        }
    }
}

// ---------------- fp32 -> bf16 hi/lo split --------------------------------------
__device__ __forceinline__ void split4(float4 v, uint2& hp, uint2& lp) {
    __nv_bfloat162 h01 = __floats2bfloat162_rn(v.x, v.y);
    __nv_bfloat162 h23 = __floats2bfloat162_rn(v.z, v.w);
    float lx = v.x - __bfloat162float(h01.x);
    float ly = v.y - __bfloat162float(h01.y);
    float lz = v.z - __bfloat162float(h23.x);
    float lw = v.w - __bfloat162float(h23.y);
    __nv_bfloat162 l01 = __floats2bfloat162_rn(lx, ly);
    __nv_bfloat162 l23 = __floats2bfloat162_rn(lz, lw);
    hp.x = *(uint32_t*)&h01; hp.y = *(uint32_t*)&h23;
    lp.x = *(uint32_t*)&l01; lp.y = *(uint32_t*)&l23;
}

__global__ void __launch_bounds__(256) convert_x(const float* __restrict__ x)
{
    int m = blockIdx.x, j = threadIdx.x * 4;
    float4 v = *(const float4*)&x[(size_t)m * DM + j];
    uint2 hp, lp; split4(v, hp, lp);
    *(uint2*)&g_xh[(size_t)m * DM + j] = hp;
    *(uint2*)&g_xl[(size_t)m * DM + j] = lp;
}

__global__ void __launch_bounds__(256) convert_w_all(
    const float* __restrict__ Wd, const float* __restrict__ WB,
    const float* __restrict__ WC, const float* __restrict__ Wc)
{
    int k = blockIdx.x, t = threadIdx.x;
    int j = t * 4;
    {
        float4 v = *(const float4*)&Wd[(size_t)k * DM + j];
        uint2 hp, lp; split4(v, hp, lp);
        *(uint2*)&g_w1[(size_t)k * NB1 + j]        = hp;
        *(uint2*)&g_w1[(size_t)(k + DM) * NB1 + j] = lp;
    }
    {
        float4 v = *(const float4*)&Wc[(size_t)k * DM + j];
        uint2 hp, lp; split4(v, hp, lp);
        *(uint2*)&g_w2[(size_t)k * DM + j]        = hp;
        *(uint2*)&g_w2[(size_t)(k + DM) * DM + j] = lp;
    }
    if (t < 128) {
        float bv = 0.f;
        if (t < SD) bv = WB[k * SD + t];
        else if (t < 2 * SD) bv = WC[k * SD + t - SD];
        __nv_bfloat16 h = __float2bfloat16(bv);
        __nv_bfloat16 l = __float2bfloat16(bv - __bfloat162float(h));
        g_w1[(size_t)k * NB1 + DM + t]        = h;
        g_w1[(size_t)(k + DM) * NB1 + DM + t] = l;
    }
}

// ---------------- chunked selective scan ------------------------------------------
#define TC 128
__global__ void __launch_bounds__(256) scan_pass1(
    const float* __restrict__ x, const float* __restrict__ A_log)
{
    int blk  = blockIdx.x;               // 2 * 64 * 15
    int c    = blk % 15;
    int rem  = blk / 15;
    int dblk = rem & 63;
    int b    = rem >> 6;
    int tid  = threadIdx.x;
    int g    = tid >> 4, n = tid & 15;
    int d0   = dblk << 4, d = d0 + g;

    __shared__ float2 s_dx[TC][16];
    __shared__ float  s_B [TC][16];

    float a2 = -__expf(A_log[d * SD + n]) * LOG2E;
    float h = 0.f, sdt = 0.f;

    const float* dbase = g_delta + ((size_t)b * SEQ) * DM + d0;
    const float* xbase = x       + ((size_t)b * SEQ) * DM + d0;
    const float* Bbase = g_Bsel  + ((size_t)b * SEQ) * SD;
    int lr = tid >> 4, lc = tid & 15;
    int tstart = c * CHL;

    for (int t0 = tstart; t0 < tstart + CHL; t0 += TC) {
        __syncthreads();
        for (int r = lr; r < TC; r += 16) {
            float dt = dbase[(size_t)(t0 + r) * DM + lc];
            float xv = xbase[(size_t)(t0 + r) * DM + lc];
            s_dx[r][lc] = make_float2(dt, dt * xv);
            s_B[r][lc]  = Bbase[(size_t)(t0 + r) * SD + lc];
        }
        __syncthreads();
#pragma unroll 8
        for (int t = 0; t < TC; t++) {
            float2 dx = s_dx[t][g];
            float bn  = s_B[t][n];
            h = fmaf(h, exp2f(dx.x * a2), dx.y * bn);
            sdt += dx.x;
        }
    }
    size_t ci = ((size_t)(b * NCH + c) * DM + d) * SD + n;
    g_hchunk[ci] = h;
    if (n == 0) g_sumdel[(size_t)(b * NCH + c) * DM + d] = sdt;
}

// pass3: per-thread h0 recombination (fused pass2) + re-scan, emit y
__global__ void __launch_bounds__(256) scan_pass3(
    const float* __restrict__ x, const float* __restrict__ A_log)
{
    int blk  = blockIdx.x;               // 2 * 64 * 16
    int c    = blk & (NCH - 1);
    int dblk = (blk >> 4) & 63;
    int b    = blk >> 10;
    int tid  = threadIdx.x;
    int g    = tid >> 4, n = tid & 15;
    int d0   = dblk << 4, d = d0 + g;

    __shared__ float2 s_dx[TC][16];
    __shared__ float2 s_bc[TC][16];
    __shared__ float  s_y [TC][16];

    float a2 = -__expf(A_log[d * SD + n]) * LOG2E;

    float h = 0.f;
    for (int cc = 0; cc < c; cc++) {
        float S = g_sumdel[(size_t)(b * NCH + cc) * DM + d];
        float F = g_hchunk[((size_t)(b * NCH + cc) * DM + d) * SD + n];
        h = fmaf(h, exp2f(a2 * S), F);
    }

    const float* dbase = g_delta + ((size_t)b * SEQ) * DM + d0;
    const float* xbase = x       + ((size_t)b * SEQ) * DM + d0;
    const float* Bbase = g_Bsel  + ((size_t)b * SEQ) * SD;
    const float* Cbase = g_Csel  + ((size_t)b * SEQ) * SD;
    float*       ybase = g_ssm   + ((size_t)b * SEQ) * DM + d0;
    int lr = tid >> 4, lc = tid & 15;
    int tstart = c * CHL;

    for (int t0 = tstart; t0 < tstart + CHL; t0 += TC) {
        __syncthreads();
        for (int r = lr; r < TC; r += 16) {
            float dt = dbase[(size_t)(t0 + r) * DM + lc];
            float xv = xbase[(size_t)(t0 + r) * DM + lc];
            s_dx[r][lc] = make_float2(dt, dt * xv);
            s_bc[r][lc] = make_float2(Bbase[(size_t)(t0 + r) * SD + lc],
                                      Cbase[(size_t)(t0 + r) * SD + lc]);
        }
        __syncthreads();
#pragma unroll 4
        for (int t = 0; t < TC; t++) {
            float2 dx = s_dx[t][g];
            float2 bc = s_bc[t][n];
            h = fmaf(h, exp2f(dx.x * a2), dx.y * bc.x);
            float p = h * bc.y;
            p += __shfl_xor_sync(0xffffffffu, p, 8);
            p += __shfl_xor_sync(0xffffffffu, p, 4);
            p += __shfl_xor_sync(0xffffffffu, p, 2);
            p += __shfl_xor_sync(0xffffffffu, p, 1);
            if (n == 0) s_y[t][g] = p;
        }
        __syncthreads();
        for (int r = lr; r < TC; r += 16)
            ybase[(size_t)(t0 + r) * DM + lc] = s_y[r][lc];
    }
}

// ---------------- layernorm -> bf16 splits + h_final ------------------------------
__global__ void __launch_bounds__(256) ln_kernel(
    const float* __restrict__ gamma, const float* __restrict__ beta)
{
    int m = blockIdx.x;
    const float* row = g_ssm + (size_t)m * DM;
    int tid = threadIdx.x;
    float4 v = *(const float4*)&row[tid * 4];
    float s  = v.x + v.y + v.z + v.w;
    float ss = v.x*v.x + v.y*v.y + v.z*v.z + v.w*v.w;
#pragma unroll
    for (int o = 16; o > 0; o >>= 1) {
        s  += __shfl_xor_sync(0xffffffffu, s,  o);
        ss += __shfl_xor_sync(0xffffffffu, ss, o);
    }
    __shared__ float rs[8], rss[8];
    if ((tid & 31) == 0) { rs[tid >> 5] = s; rss[tid >> 5] = ss; }
    __syncthreads();
    s = 0.f; ss = 0.f;
#pragma unroll
    for (int i = 0; i < 8; i++) { s += rs[i]; ss += rss[i]; }
    float mu  = s * (1.0f / DM);
    float var = ss * (1.0f / DM) - mu * mu;
    float inv = rsqrtf(var + 1e-5f);
    float4 g4 = *(const float4*)&gamma[tid * 4];
    float4 b4 = *(const float4*)&beta[tid * 4];
    v.x = (v.x - mu) * inv * g4.x + b4.x;
    v.y = (v.y - mu) * inv * g4.y + b4.y;
    v.z = (v.z - mu) * inv * g4.z + b4.z;
    v.w = (v.w - mu) * inv * g4.w + b4.w;

    uint2 hp, lp; split4(v, hp, lp);
    *(uint2*)&g_sh[(size_t)m * DM + tid * 4] = hp;
    *(uint2*)&g_sl[(size_t)m * DM + tid * 4] = lp;

    if ((m & (SEQ - 1)) == SEQ - 1) {
        int b = m / SEQ;
        *(float4*)&g_hfinal[b * DM + tid * 4] = v;
    }
}

// ---------------- h_proj = h_final @ W_imp -----------------------------------------
__global__ void __launch_bounds__(256) hproj_kernel(const float* __restrict__ Wimp)
{
    int b = blockIdx.y;
    int j = blockIdx.x * 256 + threadIdx.x;
    __shared__ float hf[DM];
    for (int i = threadIdx.x; i < DM; i += 256) hf[i] = g_hfinal[b * DM + i];
    __syncthreads();
    float a0 = 0.f, a1 = 0.f, a2 = 0.f, a3 = 0.f;
#pragma unroll 4
    for (int d = 0; d < DM; d += 4) {
        a0 = fmaf(hf[d+0], Wimp[(size_t)(d+0) * DM + j], a0);
        a1 = fmaf(hf[d+1], Wimp[(size_t)(d+1) * DM + j], a1);
        a2 = fmaf(hf[d+2], Wimp[(size_t)(d+2) * DM + j], a2);
        a3 = fmaf(hf[d+3], Wimp[(size_t)(d+3) * DM + j], a3);
    }
    g_hproj[b * DM + j] = (a0 + a1) + (a2 + a3);
}

// ---------------- raw_importance -----------------------------------------------------
__global__ void __launch_bounds__(256) raw_kernel(
    const float* __restrict__ x, float* __restrict__ out_raw)
{
    int m    = (blockIdx.x * 256 + threadIdx.x) >> 5;
    int lane = threadIdx.x & 31;
    int b    = m >> 12;
    const float* xr = x + (size_t)m * DM;
    const float* hp = g_hproj + b * DM;
    float acc = 0.f;
    for (int d = lane * 4; d < DM; d += 128) {
        float4 xv = *(const float4*)&xr[d];
        float4 hv = *(const float4*)&hp[d];
        acc += xv.x*hv.x + xv.y*hv.y + xv.z*hv.z + xv.w*hv.w;
    }
#pragma unroll
    for (int o = 16; o > 0; o >>= 1) acc += __shfl_xor_sync(0xffffffffu, acc, o);
    if (lane == 0) { g_raw[m] = acc; out_raw[m] = acc; }
}

// ---------------- softmax over seq ---------------------------------------------------
__global__ void __launch_bounds__(1024) softmax_kernel(float* __restrict__ out_imp)
{
    int b   = blockIdx.x;
    int tid = threadIdx.x;
    const float* r = g_raw + (size_t)b * SEQ;
    float4 rv = *(const float4*)&r[tid * 4];
    float v0 = rv.x * 2.0f, v1 = rv.y * 2.0f, v2 = rv.z * 2.0f, v3 = rv.w * 2.0f;
    float mx = fmaxf(fmaxf(v0, v1), fmaxf(v2, v3));

    __shared__ float swarp[32];
    __shared__ float bval;
#pragma unroll
    for (int o = 16; o > 0; o >>= 1) mx = fmaxf(mx, __shfl_xor_sync(0xffffffffu, mx, o));
    if ((tid & 31) == 0) swarp[tid >> 5] = mx;
    __syncthreads();
    if (tid < 32) {
        float v = swarp[tid];
#pragma unroll
        for (int o = 16; o > 0; o >>= 1) v = fmaxf(v, __shfl_xor_sync(0xffffffffu, v, o));
        if (tid == 0) bval = v;
    }
    __syncthreads();
    float gmax = bval;
    float e0 = __expf(v0 - gmax), e1 = __expf(v1 - gmax);
    float e2 = __expf(v2 - gmax), e3 = __expf(v3 - gmax);
    float sum = e0 + e1 + e2 + e3;
#pragma unroll
    for (int o = 16; o > 0; o >>= 1) sum += __shfl_xor_sync(0xffffffffu, sum, o);
    __syncthreads();
    if ((tid & 31) == 0) swarp[tid >> 5] = sum;
    __syncthreads();
    if (tid < 32) {
        float v = swarp[tid];
#pragma unroll
        for (int o = 16; o > 0; o >>= 1) v += __shfl_xor_sync(0xffffffffu, v, o);
        if (tid == 0) bval = v;
    }
    __syncthreads();
    float inv = 1.0f / bval;
    float4 o4; o4.x = e0 * inv; o4.y = e1 * inv; o4.z = e2 * inv; o4.w = e3 * inv;
    *(float4*)&out_imp[(size_t)b * SEQ + tid * 4] = o4;
}

// ---------------- launch ---------------------------------------------------------------
extern "C" void kernel_launch(void* const* d_in, const int* in_sizes, int n_in,
                              void* d_out, int out_size)
{
    const float* x       = (const float*)d_in[0];
    const float* A_log   = (const float*)d_in[1];
    const float* W_delta = (const float*)d_in[2];
    const float* W_B     = (const float*)d_in[3];
    const float* W_C     = (const float*)d_in[4];
    const float* gamma   = (const float*)d_in[5];
    const float* beta    = (const float*)d_in[6];
    const float* W_ctx   = (const float*)d_in[7];
    const float* scale   = (const float*)d_in[8];
    const float* W_imp   = (const float*)d_in[9];

    float* out     = (float*)d_out;
    float* out_imp = out;
    float* out_ctx = out + M_ROWS;
    float* out_raw = out + M_ROWS + (size_t)M_ROWS * DM;

    __nv_bfloat16 *p_xh, *p_xl, *p_sh, *p_sl, *p_w1, *p_w2;
    cudaGetSymbolAddress((void**)&p_xh, g_xh);
    cudaGetSymbolAddress((void**)&p_xl, g_xl);
    cudaGetSymbolAddress((void**)&p_sh, g_sh);
    cudaGetSymbolAddress((void**)&p_sl, g_sl);
    cudaGetSymbolAddress((void**)&p_w1, g_w1);
    cudaGetSymbolAddress((void**)&p_w2, g_w2);

    static cudaStream_t s_aux = nullptr;
    static cudaEvent_t ev_fork1, ev_join1, ev_fork2, ev_join2;
    static bool init_done = false;
    if (!init_done) {
        cudaFuncSetAttribute(hmma_gemm<0>, cudaFuncAttributeMaxDynamicSharedMemorySize, GSMEM);
        cudaFuncSetAttribute(hmma_gemm<1>, cudaFuncAttributeMaxDynamicSharedMemorySize, GSMEM);
        cudaStreamCreateWithFlags(&s_aux, cudaStreamNonBlocking);
        cudaEventCreateWithFlags(&ev_fork1, cudaEventDisableTiming);
        cudaEventCreateWithFlags(&ev_join1, cudaEventDisableTiming);
        cudaEventCreateWithFlags(&ev_fork2, cudaEventDisableTiming);
        cudaEventCreateWithFlags(&ev_join2, cudaEventDisableTiming);
        init_done = true;
    }

    const __nv_bfloat16* p_w1l = p_w1 + (size_t)DM * NB1;
    const __nv_bfloat16* p_w2l = p_w2 + (size_t)DM * DM;

    // fork: convert_x (aux) || convert_w_all (main)
    cudaEventRecord(ev_fork1, 0);
    cudaStreamWaitEvent(s_aux, ev_fork1, 0);
    convert_x<<<M_ROWS, 256, 0, s_aux>>>(x);
    convert_w_all<<<DM, 256>>>(W_delta, W_B, W_C, W_ctx);
    cudaEventRecord(ev_join1, s_aux);
    cudaStreamWaitEvent(0, ev_join1, 0);

    // GEMM1: delta (softplus) + B_sel + C_sel
    hmma_gemm<1><<<dim3(NB1 / 128, M_ROWS / 256), 256, GSMEM>>>(
        p_xh, p_xl, p_w1, p_w1l, nullptr, nullptr, NB1);

    // scan
    scan_pass1<<<BATCH * 64 * (NCH - 1), 256>>>(x, A_log);
    scan_pass3<<<BATCH * 64 * NCH, 256>>>(x, A_log);

    ln_kernel<<<M_ROWS, 256>>>(gamma, beta);

    // fork: importance tail (aux) || GEMM2 (main)
    cudaEventRecord(ev_fork2, 0);
    cudaStreamWaitEvent(s_aux, ev_fork2, 0);
    hproj_kernel<<<dim3(DM / 256, BATCH), 256, 0, s_aux>>>(W_imp);
    raw_kernel<<<M_ROWS / 8, 256, 0, s_aux>>>(x, out_raw);
    softmax_kernel<<<BATCH, 1024, 0, s_aux>>>(out_imp);
    cudaEventRecord(ev_join2, s_aux);

    // GEMM2: context = ln(ssm) @ W_ctx * scale
    hmma_gemm<0><<<dim3(DM / 128, M_ROWS / 256), 256, GSMEM>>>(
        p_sh, p_sl, p_w2, p_w2l, out_ctx, scale, DM);

    cudaStreamWaitEvent(0, ev_join2, 0);
}

// round 15
// speedup vs baseline: 1.0450x; 1.0450x over previous
#include <cuda_runtime.h>
#include <cuda_bf16.h>
#include <math.h>
#include <stdint.h>

#define BATCH 2
#define SEQ 4096
#define DM 1024
#define SD 16
#define M_ROWS (BATCH*SEQ)   // 8192
#define NB1 1152             // GEMM1 N (1024 delta + 16 B + 16 C + 96 pad)
#define NCH 16
#define CHL (SEQ/NCH)        // 256
#define LOG2E 1.4426950408889634f

// ---------------- scratch (device globals) -----------------------------------
__device__ float g_delta[(size_t)M_ROWS * DM];
__device__ float g_Bsel [(size_t)M_ROWS * SD];
__device__ float g_Csel [(size_t)M_ROWS * SD];
__device__ float g_ssm  [(size_t)M_ROWS * DM];
__device__ float g_hfinal[BATCH * DM];
__device__ float g_hproj [BATCH * DM];
__device__ float g_raw  [M_ROWS];
__device__ float g_hchunk[(size_t)BATCH * NCH * DM * SD];
__device__ float g_sumdel[(size_t)BATCH * NCH * DM];
__device__ __nv_bfloat16 g_xh[(size_t)M_ROWS * DM];
__device__ __nv_bfloat16 g_xl[(size_t)M_ROWS * DM];
__device__ __nv_bfloat16 g_sh[(size_t)M_ROWS * DM];
__device__ __nv_bfloat16 g_sl[(size_t)M_ROWS * DM];
__device__ __nv_bfloat16 g_w1[(size_t)2 * DM * NB1];     // [k<1024 hi][k+1024 lo]
__device__ __nv_bfloat16 g_w2[(size_t)2 * DM * DM];      // W_ctx hi/lo

// ---------------- PTX helpers ------------------------------------------------
__device__ __forceinline__ void ldsm_x4(uint32_t r[4], uint32_t addr) {
    asm volatile("ldmatrix.sync.aligned.m8n8.x4.shared.b16 {%0,%1,%2,%3}, [%4];\n"
        : "=r"(r[0]), "=r"(r[1]), "=r"(r[2]), "=r"(r[3]) : "r"(addr));
}
__device__ __forceinline__ void ldsm_x4_t(uint32_t r[4], uint32_t addr) {
    asm volatile("ldmatrix.sync.aligned.m8n8.x4.trans.shared.b16 {%0,%1,%2,%3}, [%4];\n"
        : "=r"(r[0]), "=r"(r[1]), "=r"(r[2]), "=r"(r[3]) : "r"(addr));
}
__device__ __forceinline__ void mma_bf16(float c[4], const uint32_t a[4],
                                         uint32_t b0, uint32_t b1) {
    asm volatile("mma.sync.aligned.m16n8k16.row.col.f32.bf16.bf16.f32 "
        "{%0,%1,%2,%3}, {%4,%5,%6,%7}, {%8,%9}, {%0,%1,%2,%3};\n"
        : "+f"(c[0]), "+f"(c[1]), "+f"(c[2]), "+f"(c[3])
        : "r"(a[0]), "r"(a[1]), "r"(a[2]), "r"(a[3]), "r"(b0), "r"(b1));
}
__device__ __forceinline__ void cp16(uint32_t saddr, const void* gaddr) {
    asm volatile("cp.async.cg.shared.global [%0], [%1], 16;\n" :: "r"(saddr), "l"(gaddr));
}

// ---------------- GEMM smem layout (3-stage, 128x128 block) ---------------------
#define ASTG 10240                   // 128*40*2
#define BSTG 8704                    // 32*136*2
#define STGB (2*ASTG + 2*BSTG)       // 37888 per stage
#define GSMEM (3*STGB)               // 113664

// ---------------- dual-split bf16 HMMA GEMM ------------------------------------
// Block 128x128, 8 warps (2x4), warp tile 64x32. 3 passes: AhBh + AhBl + AlBh.
template<int MODE>
__global__ void __launch_bounds__(256, 2) hmma_gemm(
    const __nv_bfloat16* __restrict__ Ahg, const __nv_bfloat16* __restrict__ Alg,
    const __nv_bfloat16* __restrict__ Bhg, const __nv_bfloat16* __restrict__ Blg,
    float* __restrict__ C, const float* __restrict__ scale_ptr, int N)
{
    extern __shared__ char smem[];
    uint32_t sb = (uint32_t)__cvta_generic_to_shared(smem);

    const int tid  = threadIdx.x;
    const int warp = tid >> 5, lane = tid & 31;
    const int wm = warp >> 2, wn = warp & 3;
    const int brow = blockIdx.y * 128, bcol = blockIdx.x * 128;

    float acc[4][4][4];
#pragma unroll
    for (int i = 0; i < 4; i++)
#pragma unroll
        for (int j = 0; j < 4; j++)
#pragma unroll
            for (int c = 0; c < 4; c++) acc[i][j][c] = 0.f;

    const __nv_bfloat16* Ah = Ahg + (size_t)brow * DM;
    const __nv_bfloat16* Al = Alg + (size_t)brow * DM;
    const __nv_bfloat16* Bh = Bhg + bcol;
    const __nv_bfloat16* Bl = Blg + bcol;

    const uint32_t a_base = (uint32_t)(((wm * 64 + (lane & 15)) * 40 + (lane >> 4) * 8) * 2);
    const uint32_t b_base = (uint32_t)((((lane & 15)) * 136 + wn * 32 + (lane >> 4) * 8) * 2);

    auto load_stage = [&](int s, int k0) {
        uint32_t base = sb + (uint32_t)(s * STGB);
#pragma unroll
        for (int i = 0; i < 2; i++) {              // A tiles: 128 x 32
            int idx = tid + i * 256;
            int r = idx >> 2, c = (idx & 3) * 8;
            uint32_t so = (uint32_t)((r * 40 + c) * 2);
            const size_t go = (size_t)r * DM + k0 + c;
            cp16(base + so,        Ah + go);
            cp16(base + ASTG + so, Al + go);
        }
#pragma unroll
        for (int i = 0; i < 2; i++) {              // B tiles: 32 x 128
            int idx = tid + i * 256;
            int r = idx >> 4, c = (idx & 15) * 8;
            uint32_t so = (uint32_t)((r * 136 + c) * 2);
            const size_t go = (size_t)(k0 + r) * N + c;
            cp16(base + 2 * ASTG + so,        Bh + go);
            cp16(base + 2 * ASTG + BSTG + so, Bl + go);
        }
    };

    load_stage(0, 0);
    asm volatile("cp.async.commit_group;\n");
    load_stage(1, 32);
    asm volatile("cp.async.commit_group;\n");

    const int NK = DM / 32;   // 32
    int s = 0;
    for (int kt = 0; kt < NK; kt++) {
        asm volatile("cp.async.wait_group 1;\n");
        __syncthreads();
        if (kt + 2 < NK) {
            int s2 = s + 2; if (s2 >= 3) s2 -= 3;
            load_stage(s2, (kt + 2) * 32);
        }
        asm volatile("cp.async.commit_group;\n");

        uint32_t stg = sb + (uint32_t)(s * STGB);
        uint32_t sAh = stg + a_base;
        uint32_t sAl = stg + ASTG + a_base;
        uint32_t sBh = stg + 2 * ASTG + b_base;
        uint32_t sBl = stg + 2 * ASTG + BSTG + b_base;
#pragma unroll
        for (int kk = 0; kk < 2; kk++) {
            const uint32_t ao = kk * 32;
            const uint32_t bo = kk * 4352;

            uint32_t ah[4][4];
#pragma unroll
            for (int mt = 0; mt < 4; mt++)
                ldsm_x4(ah[mt], sAh + ao + (uint32_t)(mt * 1280));
            uint32_t bh_[2][4];
            ldsm_x4_t(bh_[0], sBh + bo);
            ldsm_x4_t(bh_[1], sBh + bo + 32);
            uint32_t bl_[2][4];
            ldsm_x4_t(bl_[0], sBl + bo);
            ldsm_x4_t(bl_[1], sBl + bo + 32);

#pragma unroll
            for (int mt = 0; mt < 4; mt++)
#pragma unroll
                for (int nt = 0; nt < 4; nt++)
                    mma_bf16(acc[mt][nt], ah[mt],
                             bh_[nt >> 1][(nt & 1) * 2], bh_[nt >> 1][(nt & 1) * 2 + 1]);
#pragma unroll
            for (int mt = 0; mt < 4; mt++)
#pragma unroll
                for (int nt = 0; nt < 4; nt++)
                    mma_bf16(acc[mt][nt], ah[mt],
                             bl_[nt >> 1][(nt & 1) * 2], bl_[nt >> 1][(nt & 1) * 2 + 1]);

            uint32_t al[4][4];
#pragma unroll
            for (int mt = 0; mt < 4; mt++)
                ldsm_x4(al[mt], sAl + ao + (uint32_t)(mt * 1280));
#pragma unroll
            for (int mt = 0; mt < 4; mt++)
#pragma unroll
                for (int nt = 0; nt < 4; nt++)
                    mma_bf16(acc[mt][nt], al[mt],
                             bh_[nt >> 1][(nt & 1) * 2], bh_[nt >> 1][(nt & 1) * 2 + 1]);
        }
        if (++s >= 3) s -= 3;
    }

    float scl = 1.0f;
    if (MODE == 0 && scale_ptr) scl = *scale_ptr;
    const int g = lane >> 2, tg = lane & 3;
#pragma unroll
    for (int mt = 0; mt < 4; mt++) {
#pragma unroll
        for (int nt = 0; nt < 4; nt++) {
            int col = bcol + wn * 32 + nt * 8 + tg * 2;
#pragma unroll
            for (int half = 0; half < 2; half++) {
                int row = brow + wm * 64 + mt * 16 + g + half * 8;
                float v0 = acc[mt][nt][half * 2], v1 = acc[mt][nt][half * 2 + 1];
                if (MODE == 0) {
                    *(float2*)&C[(size_t)row * DM + col] = make_float2(v0 * scl, v1 * scl);
                } else {
                    if (col < DM) {
                        v0 = fmaxf(v0, 0.f) + log1pf(__expf(-fabsf(v0)));
                        v1 = fmaxf(v1, 0.f) + log1pf(__expf(-fabsf(v1)));
                        *(float2*)&g_delta[(size_t)row * DM + col] = make_float2(v0, v1);
                    } else if (col < DM + SD) {
                        *(float2*)&g_Bsel[(size_t)row * SD + col - DM] = make_float2(v0, v1);
                    } else if (col < DM + 2 * SD) {
                        *(float2*)&g_Csel[(size_t)row * SD + col - DM - SD] = make_float2(v0, v1);
                    }
                }
            }
        }
    }
}

// ---------------- fp32 -> bf16 hi/lo split --------------------------------------
__device__ __forceinline__ void split4(float4 v, uint2& hp, uint2& lp) {
    __nv_bfloat162 h01 = __floats2bfloat162_rn(v.x, v.y);
    __nv_bfloat162 h23 = __floats2bfloat162_rn(v.z, v.w);
    float lx = v.x - __bfloat162float(h01.x);
    float ly = v.y - __bfloat162float(h01.y);
    float lz = v.z - __bfloat162float(h23.x);
    float lw = v.w - __bfloat162float(h23.y);
    __nv_bfloat162 l01 = __floats2bfloat162_rn(lx, ly);
    __nv_bfloat162 l23 = __floats2bfloat162_rn(lz, lw);
    hp.x = *(uint32_t*)&h01; hp.y = *(uint32_t*)&h23;
    lp.x = *(uint32_t*)&l01; lp.y = *(uint32_t*)&l23;
}

__global__ void __launch_bounds__(256) convert_x(const float* __restrict__ x)
{
    int m = blockIdx.x, j = threadIdx.x * 4;
    float4 v = *(const float4*)&x[(size_t)m * DM + j];
    uint2 hp, lp; split4(v, hp, lp);
    *(uint2*)&g_xh[(size_t)m * DM + j] = hp;
    *(uint2*)&g_xl[(size_t)m * DM + j] = lp;
}

__global__ void __launch_bounds__(256) convert_w_all(
    const float* __restrict__ Wd, const float* __restrict__ WB,
    const float* __restrict__ WC, const float* __restrict__ Wc)
{
    int k = blockIdx.x, t = threadIdx.x;
    int j = t * 4;
    {
        float4 v = *(const float4*)&Wd[(size_t)k * DM + j];
        uint2 hp, lp; split4(v, hp, lp);
        *(uint2*)&g_w1[(size_t)k * NB1 + j]        = hp;
        *(uint2*)&g_w1[(size_t)(k + DM) * NB1 + j] = lp;
    }
    {
        float4 v = *(const float4*)&Wc[(size_t)k * DM + j];
        uint2 hp, lp; split4(v, hp, lp);
        *(uint2*)&g_w2[(size_t)k * DM + j]        = hp;
        *(uint2*)&g_w2[(size_t)(k + DM) * DM + j] = lp;
    }
    if (t < 128) {
        float bv = 0.f;
        if (t < SD) bv = WB[k * SD + t];
        else if (t < 2 * SD) bv = WC[k * SD + t - SD];
        __nv_bfloat16 h = __float2bfloat16(bv);
        __nv_bfloat16 l = __float2bfloat16(bv - __bfloat162float(h));
        g_w1[(size_t)k * NB1 + DM + t]        = h;
        g_w1[(size_t)(k + DM) * NB1 + DM + t] = l;
    }
}

// ---------------- chunked selective scan ------------------------------------------
#define TC 128
__global__ void __launch_bounds__(256) scan_pass1(
    const float* __restrict__ x, const float* __restrict__ A_log)
{
    int blk  = blockIdx.x;               // 2 * 64 * 15
    int c    = blk % 15;
    int rem  = blk / 15;
    int dblk = rem & 63;
    int b    = rem >> 6;
    int tid  = threadIdx.x;
    int g    = tid >> 4, n = tid & 15;
    int d0   = dblk << 4, d = d0 + g;

    __shared__ float2 s_dx[TC][16];
    __shared__ float  s_B [TC][16];

    float a2 = -__expf(A_log[d * SD + n]) * LOG2E;
    float h = 0.f, sdt = 0.f;

    const float* dbase = g_delta + ((size_t)b * SEQ) * DM + d0;
    const float* xbase = x       + ((size_t)b * SEQ) * DM + d0;
    const float* Bbase = g_Bsel  + ((size_t)b * SEQ) * SD;
    int lr = tid >> 4, lc = tid & 15;
    int tstart = c * CHL;

    for (int t0 = tstart; t0 < tstart + CHL; t0 += TC) {
        __syncthreads();
        for (int r = lr; r < TC; r += 16) {
            float dt = dbase[(size_t)(t0 + r) * DM + lc];
            float xv = xbase[(size_t)(t0 + r) * DM + lc];
            s_dx[r][lc] = make_float2(dt, dt * xv);
            s_B[r][lc]  = Bbase[(size_t)(t0 + r) * SD + lc];
        }
        __syncthreads();
#pragma unroll 8
        for (int t = 0; t < TC; t++) {
            float2 dx = s_dx[t][g];
            float bn  = s_B[t][n];
            h = fmaf(h, exp2f(dx.x * a2), dx.y * bn);
            sdt += dx.x;
        }
    }
    size_t ci = ((size_t)(b * NCH + c) * DM + d) * SD + n;
    g_hchunk[ci] = h;
    if (n == 0) g_sumdel[(size_t)(b * NCH + c) * DM + d] = sdt;
}

// pass3: per-thread h0 recombination (fused pass2) + re-scan, emit y
__global__ void __launch_bounds__(256) scan_pass3(
    const float* __restrict__ x, const float* __restrict__ A_log)
{
    int blk  = blockIdx.x;               // 2 * 64 * 16
    int c    = blk & (NCH - 1);
    int dblk = (blk >> 4) & 63;
    int b    = blk >> 10;
    int tid  = threadIdx.x;
    int g    = tid >> 4, n = tid & 15;
    int d0   = dblk << 4, d = d0 + g;

    __shared__ float2 s_dx[TC][16];
    __shared__ float2 s_bc[TC][16];
    __shared__ float  s_y [TC][16];

    float a2 = -__expf(A_log[d * SD + n]) * LOG2E;

    float h = 0.f;
    for (int cc = 0; cc < c; cc++) {
        float S = g_sumdel[(size_t)(b * NCH + cc) * DM + d];
        float F = g_hchunk[((size_t)(b * NCH + cc) * DM + d) * SD + n];
        h = fmaf(h, exp2f(a2 * S), F);
    }

    const float* dbase = g_delta + ((size_t)b * SEQ) * DM + d0;
    const float* xbase = x       + ((size_t)b * SEQ) * DM + d0;
    const float* Bbase = g_Bsel  + ((size_t)b * SEQ) * SD;
    const float* Cbase = g_Csel  + ((size_t)b * SEQ) * SD;
    float*       ybase = g_ssm   + ((size_t)b * SEQ) * DM + d0;
    int lr = tid >> 4, lc = tid & 15;
    int tstart = c * CHL;

    for (int t0 = tstart; t0 < tstart + CHL; t0 += TC) {
        __syncthreads();
        for (int r = lr; r < TC; r += 16) {
            float dt = dbase[(size_t)(t0 + r) * DM + lc];
            float xv = xbase[(size_t)(t0 + r) * DM + lc];
            s_dx[r][lc] = make_float2(dt, dt * xv);
            s_bc[r][lc] = make_float2(Bbase[(size_t)(t0 + r) * SD + lc],
                                      Cbase[(size_t)(t0 + r) * SD + lc]);
        }
        __syncthreads();
#pragma unroll 4
        for (int t = 0; t < TC; t++) {
            float2 dx = s_dx[t][g];
            float2 bc = s_bc[t][n];
            h = fmaf(h, exp2f(dx.x * a2), dx.y * bc.x);
            float p = h * bc.y;
            p += __shfl_xor_sync(0xffffffffu, p, 8);
            p += __shfl_xor_sync(0xffffffffu, p, 4);
            p += __shfl_xor_sync(0xffffffffu, p, 2);
            p += __shfl_xor_sync(0xffffffffu, p, 1);
            if (n == 0) s_y[t][g] = p;
        }
        __syncthreads();
        for (int r = lr; r < TC; r += 16)
            ybase[(size_t)(t0 + r) * DM + lc] = s_y[r][lc];
    }
}

// ---------------- layernorm -> bf16 splits + h_final ------------------------------
__global__ void __launch_bounds__(256) ln_kernel(
    const float* __restrict__ gamma, const float* __restrict__ beta)
{
    int m = blockIdx.x;
    const float* row = g_ssm + (size_t)m * DM;
    int tid = threadIdx.x;
    float4 v = *(const float4*)&row[tid * 4];
    float s  = v.x + v.y + v.z + v.w;
    float ss = v.x*v.x + v.y*v.y + v.z*v.z + v.w*v.w;
#pragma unroll
    for (int o = 16; o > 0; o >>= 1) {
        s  += __shfl_xor_sync(0xffffffffu, s,  o);
        ss += __shfl_xor_sync(0xffffffffu, ss, o);
    }
    __shared__ float rs[8], rss[8];
    if ((tid & 31) == 0) { rs[tid >> 5] = s; rss[tid >> 5] = ss; }
    __syncthreads();
    s = 0.f; ss = 0.f;
#pragma unroll
    for (int i = 0; i < 8; i++) { s += rs[i]; ss += rss[i]; }
    float mu  = s * (1.0f / DM);
    float var = ss * (1.0f / DM) - mu * mu;
    float inv = rsqrtf(var + 1e-5f);
    float4 g4 = *(const float4*)&gamma[tid * 4];
    float4 b4 = *(const float4*)&beta[tid * 4];
    v.x = (v.x - mu) * inv * g4.x + b4.x;
    v.y = (v.y - mu) * inv * g4.y + b4.y;
    v.z = (v.z - mu) * inv * g4.z + b4.z;
    v.w = (v.w - mu) * inv * g4.w + b4.w;

    uint2 hp, lp; split4(v, hp, lp);
    *(uint2*)&g_sh[(size_t)m * DM + tid * 4] = hp;
    *(uint2*)&g_sl[(size_t)m * DM + tid * 4] = lp;

    if ((m & (SEQ - 1)) == SEQ - 1) {
        int b = m / SEQ;
        *(float4*)&g_hfinal[b * DM + tid * 4] = v;
    }
}

// ---------------- h_proj = h_final @ W_imp -----------------------------------------
__global__ void __launch_bounds__(256) hproj_kernel(const float* __restrict__ Wimp)
{
    int b = blockIdx.y;
    int j = blockIdx.x * 256 + threadIdx.x;
    __shared__ float hf[DM];
    for (int i = threadIdx.x; i < DM; i += 256) hf[i] = g_hfinal[b * DM + i];
    __syncthreads();
    float a0 = 0.f, a1 = 0.f, a2 = 0.f, a3 = 0.f;
#pragma unroll 4
    for (int d = 0; d < DM; d += 4) {
        a0 = fmaf(hf[d+0], Wimp[(size_t)(d+0) * DM + j], a0);
        a1 = fmaf(hf[d+1], Wimp[(size_t)(d+1) * DM + j], a1);
        a2 = fmaf(hf[d+2], Wimp[(size_t)(d+2) * DM + j], a2);
        a3 = fmaf(hf[d+3], Wimp[(size_t)(d+3) * DM + j], a3);
    }
    g_hproj[b * DM + j] = (a0 + a1) + (a2 + a3);
}

// ---------------- raw_importance -----------------------------------------------------
__global__ void __launch_bounds__(256) raw_kernel(
    const float* __restrict__ x, float* __restrict__ out_raw)
{
    int m    = (blockIdx.x * 256 + threadIdx.x) >> 5;
    int lane = threadIdx.x & 31;
    int b    = m >> 12;
    const float* xr = x + (size_t)m * DM;
    const float* hp = g_hproj + b * DM;
    float acc = 0.f;
    for (int d = lane * 4; d < DM; d += 128) {
        float4 xv = *(const float4*)&xr[d];
        float4 hv = *(const float4*)&hp[d];
        acc += xv.x*hv.x + xv.y*hv.y + xv.z*hv.z + xv.w*hv.w;
    }
#pragma unroll
    for (int o = 16; o > 0; o >>= 1) acc += __shfl_xor_sync(0xffffffffu, acc, o);
    if (lane == 0) { g_raw[m] = acc; out_raw[m] = acc; }
}

// ---------------- softmax over seq ---------------------------------------------------
__global__ void __launch_bounds__(1024) softmax_kernel(float* __restrict__ out_imp)
{
    int b   = blockIdx.x;
    int tid = threadIdx.x;
    const float* r = g_raw + (size_t)b * SEQ;
    float4 rv = *(const float4*)&r[tid * 4];
    float v0 = rv.x * 2.0f, v1 = rv.y * 2.0f, v2 = rv.z * 2.0f, v3 = rv.w * 2.0f;
    float mx = fmaxf(fmaxf(v0, v1), fmaxf(v2, v3));

    __shared__ float swarp[32];
    __shared__ float bval;
#pragma unroll
    for (int o = 16; o > 0; o >>= 1) mx = fmaxf(mx, __shfl_xor_sync(0xffffffffu, mx, o));
    if ((tid & 31) == 0) swarp[tid >> 5] = mx;
    __syncthreads();
    if (tid < 32) {
        float v = swarp[tid];
#pragma unroll
        for (int o = 16; o > 0; o >>= 1) v = fmaxf(v, __shfl_xor_sync(0xffffffffu, v, o));
        if (tid == 0) bval = v;
    }
    __syncthreads();
    float gmax = bval;
    float e0 = __expf(v0 - gmax), e1 = __expf(v1 - gmax);
    float e2 = __expf(v2 - gmax), e3 = __expf(v3 - gmax);
    float sum = e0 + e1 + e2 + e3;
#pragma unroll
    for (int o = 16; o > 0; o >>= 1) sum += __shfl_xor_sync(0xffffffffu, sum, o);
    __syncthreads();
    if ((tid & 31) == 0) swarp[tid >> 5] = sum;
    __syncthreads();
    if (tid < 32) {
        float v = swarp[tid];
#pragma unroll
        for (int o = 16; o > 0; o >>= 1) v += __shfl_xor_sync(0xffffffffu, v, o);
        if (tid == 0) bval = v;
    }
    __syncthreads();
    float inv = 1.0f / bval;
    float4 o4; o4.x = e0 * inv; o4.y = e1 * inv; o4.z = e2 * inv; o4.w = e3 * inv;
    *(float4*)&out_imp[(size_t)b * SEQ + tid * 4] = o4;
}

// ---------------- launch ---------------------------------------------------------------
extern "C" void kernel_launch(void* const* d_in, const int* in_sizes, int n_in,
                              void* d_out, int out_size)
{
    const float* x       = (const float*)d_in[0];
    const float* A_log   = (const float*)d_in[1];
    const float* W_delta = (const float*)d_in[2];
    const float* W_B     = (const float*)d_in[3];
    const float* W_C     = (const float*)d_in[4];
    const float* gamma   = (const float*)d_in[5];
    const float* beta    = (const float*)d_in[6];
    const float* W_ctx   = (const float*)d_in[7];
    const float* scale   = (const float*)d_in[8];
    const float* W_imp   = (const float*)d_in[9];

    float* out     = (float*)d_out;
    float* out_imp = out;
    float* out_ctx = out + M_ROWS;
    float* out_raw = out + M_ROWS + (size_t)M_ROWS * DM;

    __nv_bfloat16 *p_xh, *p_xl, *p_sh, *p_sl, *p_w1, *p_w2;
    cudaGetSymbolAddress((void**)&p_xh, g_xh);
    cudaGetSymbolAddress((void**)&p_xl, g_xl);
    cudaGetSymbolAddress((void**)&p_sh, g_sh);
    cudaGetSymbolAddress((void**)&p_sl, g_sl);
    cudaGetSymbolAddress((void**)&p_w1, g_w1);
    cudaGetSymbolAddress((void**)&p_w2, g_w2);

    static cudaStream_t s_aux = nullptr;
    static cudaEvent_t ev_fork1, ev_join1, ev_fork2, ev_join2;
    static bool init_done = false;
    if (!init_done) {
        cudaFuncSetAttribute(hmma_gemm<0>, cudaFuncAttributeMaxDynamicSharedMemorySize, GSMEM);
        cudaFuncSetAttribute(hmma_gemm<1>, cudaFuncAttributeMaxDynamicSharedMemorySize, GSMEM);
        cudaStreamCreateWithFlags(&s_aux, cudaStreamNonBlocking);
        cudaEventCreateWithFlags(&ev_fork1, cudaEventDisableTiming);
        cudaEventCreateWithFlags(&ev_join1, cudaEventDisableTiming);
        cudaEventCreateWithFlags(&ev_fork2, cudaEventDisableTiming);
        cudaEventCreateWithFlags(&ev_join2, cudaEventDisableTiming);
        init_done = true;
    }

    const __nv_bfloat16* p_w1l = p_w1 + (size_t)DM * NB1;
    const __nv_bfloat16* p_w2l = p_w2 + (size_t)DM * DM;

    // fork: convert_x (aux) || convert_w_all (main)
    cudaEventRecord(ev_fork1, 0);
    cudaStreamWaitEvent(s_aux, ev_fork1, 0);
    convert_x<<<M_ROWS, 256, 0, s_aux>>>(x);
    convert_w_all<<<DM, 256>>>(W_delta, W_B, W_C, W_ctx);
    cudaEventRecord(ev_join1, s_aux);
    cudaStreamWaitEvent(0, ev_join1, 0);

    // GEMM1: delta (softplus) + B_sel + C_sel
    hmma_gemm<1><<<dim3(NB1 / 128, M_ROWS / 128), 256, GSMEM>>>(
        p_xh, p_xl, p_w1, p_w1l, nullptr, nullptr, NB1);

    // scan
    scan_pass1<<<BATCH * 64 * (NCH - 1), 256>>>(x, A_log);
    scan_pass3<<<BATCH * 64 * NCH, 256>>>(x, A_log);

    ln_kernel<<<M_ROWS, 256>>>(gamma, beta);

    // fork: importance tail (aux) || GEMM2 (main)
    cudaEventRecord(ev_fork2, 0);
    cudaStreamWaitEvent(s_aux, ev_fork2, 0);
    hproj_kernel<<<dim3(DM / 256, BATCH), 256, 0, s_aux>>>(W_imp);
    raw_kernel<<<M_ROWS / 8, 256, 0, s_aux>>>(x, out_raw);
    softmax_kernel<<<BATCH, 1024, 0, s_aux>>>(out_imp);
    cudaEventRecord(ev_join2, s_aux);

    // GEMM2: context = ln(ssm) @ W_ctx * scale
    hmma_gemm<0><<<dim3(DM / 128, M_ROWS / 128), 256, GSMEM>>>(
        p_sh, p_sl, p_w2, p_w2l, out_ctx, scale, DM);

    cudaStreamWaitEvent(0, ev_join2, 0);
}

// round 16
// speedup vs baseline: 1.1824x; 1.1314x over previous
#include <cuda_runtime.h>
#include <cuda_bf16.h>
#include <math.h>
#include <stdint.h>

#define BATCH 2
#define SEQ 4096
#define DM 1024
#define SD 16
#define M_ROWS (BATCH*SEQ)   // 8192
#define NB1 1152             // GEMM1 N (1024 delta + 16 B + 16 C + 96 pad)
#define NCH 16
#define CHL (SEQ/NCH)        // 256
#define LOG2E 1.4426950408889634f

// ---------------- scratch (device globals) -----------------------------------
__device__ float g_delta[(size_t)M_ROWS * DM];
__device__ float g_Bsel [(size_t)M_ROWS * SD];
__device__ float g_Csel [(size_t)M_ROWS * SD];
__device__ float g_ssm  [(size_t)M_ROWS * DM];
__device__ float g_hfinal[BATCH * DM];
__device__ float g_hproj [BATCH * DM];
__device__ float g_raw  [M_ROWS];
__device__ float g_hchunk[(size_t)BATCH * NCH * DM * SD];
__device__ float g_sumdel[(size_t)BATCH * NCH * DM];
__device__ __nv_bfloat16 g_xh[(size_t)M_ROWS * DM];
__device__ __nv_bfloat16 g_xl[(size_t)M_ROWS * DM];
__device__ __nv_bfloat16 g_sh[(size_t)M_ROWS * DM];
__device__ __nv_bfloat16 g_sl[(size_t)M_ROWS * DM];
__device__ __nv_bfloat16 g_w1[(size_t)2 * DM * NB1];     // [k<1024 hi][k+1024 lo]
__device__ __nv_bfloat16 g_w2[(size_t)2 * DM * DM];      // W_ctx hi/lo

// ---------------- PTX helpers ------------------------------------------------
__device__ __forceinline__ void ldsm_x4(uint32_t r[4], uint32_t addr) {
    asm volatile("ldmatrix.sync.aligned.m8n8.x4.shared.b16 {%0,%1,%2,%3}, [%4];\n"
        : "=r"(r[0]), "=r"(r[1]), "=r"(r[2]), "=r"(r[3]) : "r"(addr));
}
__device__ __forceinline__ void ldsm_x4_t(uint32_t r[4], uint32_t addr) {
    asm volatile("ldmatrix.sync.aligned.m8n8.x4.trans.shared.b16 {%0,%1,%2,%3}, [%4];\n"
        : "=r"(r[0]), "=r"(r[1]), "=r"(r[2]), "=r"(r[3]) : "r"(addr));
}
__device__ __forceinline__ void mma_bf16(float c[4], const uint32_t a[4],
                                         uint32_t b0, uint32_t b1) {
    asm volatile("mma.sync.aligned.m16n8k16.row.col.f32.bf16.bf16.f32 "
        "{%0,%1,%2,%3}, {%4,%5,%6,%7}, {%8,%9}, {%0,%1,%2,%3};\n"
        : "+f"(c[0]), "+f"(c[1]), "+f"(c[2]), "+f"(c[3])
        : "r"(a[0]), "r"(a[1]), "r"(a[2]), "r"(a[3]), "r"(b0), "r"(b1));
}
__device__ __forceinline__ void cp16(uint32_t saddr, const void* gaddr) {
    asm volatile("cp.async.cg.shared.global [%0], [%1], 16;\n" :: "r"(saddr), "l"(gaddr));
}

// ---------------- GEMM smem layout (3-stage, 128x128 block) ---------------------
#define ASTG 10240                   // 128*40*2
#define BSTG 8704                    // 32*136*2
#define STGB (2*ASTG + 2*BSTG)       // 37888 per stage
#define GSMEM (3*STGB)               // 113664

// ---------------- dual-split bf16 HMMA GEMM (champion config) -------------------
template<int MODE>
__global__ void __launch_bounds__(256, 2) hmma_gemm(
    const __nv_bfloat16* __restrict__ Ahg, const __nv_bfloat16* __restrict__ Alg,
    const __nv_bfloat16* __restrict__ Bhg, const __nv_bfloat16* __restrict__ Blg,
    float* __restrict__ C, const float* __restrict__ scale_ptr, int N)
{
    extern __shared__ char smem[];
    uint32_t sb = (uint32_t)__cvta_generic_to_shared(smem);

    const int tid  = threadIdx.x;
    const int warp = tid >> 5, lane = tid & 31;
    const int wm = warp >> 2, wn = warp & 3;
    const int brow = blockIdx.y * 128, bcol = blockIdx.x * 128;

    float acc[4][4][4];
#pragma unroll
    for (int i = 0; i < 4; i++)
#pragma unroll
        for (int j = 0; j < 4; j++)
#pragma unroll
            for (int c = 0; c < 4; c++) acc[i][j][c] = 0.f;

    const __nv_bfloat16* Ah = Ahg + (size_t)brow * DM;
    const __nv_bfloat16* Al = Alg + (size_t)brow * DM;
    const __nv_bfloat16* Bh = Bhg + bcol;
    const __nv_bfloat16* Bl = Blg + bcol;

    const uint32_t a_base = (uint32_t)(((wm * 64 + (lane & 15)) * 40 + (lane >> 4) * 8) * 2);
    const uint32_t b_base = (uint32_t)((((lane & 15)) * 136 + wn * 32 + (lane >> 4) * 8) * 2);

    auto load_stage = [&](int s, int k0) {
        uint32_t base = sb + (uint32_t)(s * STGB);
#pragma unroll
        for (int i = 0; i < 2; i++) {
            int idx = tid + i * 256;
            int r = idx >> 2, c = (idx & 3) * 8;
            uint32_t so = (uint32_t)((r * 40 + c) * 2);
            const size_t go = (size_t)r * DM + k0 + c;
            cp16(base + so,        Ah + go);
            cp16(base + ASTG + so, Al + go);
        }
#pragma unroll
        for (int i = 0; i < 2; i++) {
            int idx = tid + i * 256;
            int r = idx >> 4, c = (idx & 15) * 8;
            uint32_t so = (uint32_t)((r * 136 + c) * 2);
            const size_t go = (size_t)(k0 + r) * N + c;
            cp16(base + 2 * ASTG + so,        Bh + go);
            cp16(base + 2 * ASTG + BSTG + so, Bl + go);
        }
    };

    load_stage(0, 0);
    asm volatile("cp.async.commit_group;\n");
    load_stage(1, 32);
    asm volatile("cp.async.commit_group;\n");

    const int NK = DM / 32;
    int s = 0;
    for (int kt = 0; kt < NK; kt++) {
        asm volatile("cp.async.wait_group 1;\n");
        __syncthreads();
        if (kt + 2 < NK) {
            int s2 = s + 2; if (s2 >= 3) s2 -= 3;
            load_stage(s2, (kt + 2) * 32);
        }
        asm volatile("cp.async.commit_group;\n");

        uint32_t stg = sb + (uint32_t)(s * STGB);
        uint32_t sAh = stg + a_base;
        uint32_t sAl = stg + ASTG + a_base;
        uint32_t sBh = stg + 2 * ASTG + b_base;
        uint32_t sBl = stg + 2 * ASTG + BSTG + b_base;
#pragma unroll
        for (int kk = 0; kk < 2; kk++) {
            const uint32_t ao = kk * 32;
            const uint32_t bo = kk * 4352;

            uint32_t ah[4][4];
#pragma unroll
            for (int mt = 0; mt < 4; mt++)
                ldsm_x4(ah[mt], sAh + ao + (uint32_t)(mt * 1280));
            uint32_t bh_[2][4];
            ldsm_x4_t(bh_[0], sBh + bo);
            ldsm_x4_t(bh_[1], sBh + bo + 32);
            uint32_t bl_[2][4];
            ldsm_x4_t(bl_[0], sBl + bo);
            ldsm_x4_t(bl_[1], sBl + bo + 32);

#pragma unroll
            for (int mt = 0; mt < 4; mt++)
#pragma unroll
                for (int nt = 0; nt < 4; nt++)
                    mma_bf16(acc[mt][nt], ah[mt],
                             bh_[nt >> 1][(nt & 1) * 2], bh_[nt >> 1][(nt & 1) * 2 + 1]);
#pragma unroll
            for (int mt = 0; mt < 4; mt++)
#pragma unroll
                for (int nt = 0; nt < 4; nt++)
                    mma_bf16(acc[mt][nt], ah[mt],
                             bl_[nt >> 1][(nt & 1) * 2], bl_[nt >> 1][(nt & 1) * 2 + 1]);

            uint32_t al[4][4];
#pragma unroll
            for (int mt = 0; mt < 4; mt++)
                ldsm_x4(al[mt], sAl + ao + (uint32_t)(mt * 1280));
#pragma unroll
            for (int mt = 0; mt < 4; mt++)
#pragma unroll
                for (int nt = 0; nt < 4; nt++)
                    mma_bf16(acc[mt][nt], al[mt],
                             bh_[nt >> 1][(nt & 1) * 2], bh_[nt >> 1][(nt & 1) * 2 + 1]);
        }
        if (++s >= 3) s -= 3;
    }

    float scl = 1.0f;
    if (MODE == 0 && scale_ptr) scl = *scale_ptr;
    const int g = lane >> 2, tg = lane & 3;
#pragma unroll
    for (int mt = 0; mt < 4; mt++) {
#pragma unroll
        for (int nt = 0; nt < 4; nt++) {
            int col = bcol + wn * 32 + nt * 8 + tg * 2;
#pragma unroll
            for (int half = 0; half < 2; half++) {
                int row = brow + wm * 64 + mt * 16 + g + half * 8;
                float v0 = acc[mt][nt][half * 2], v1 = acc[mt][nt][half * 2 + 1];
                if (MODE == 0) {
                    *(float2*)&C[(size_t)row * DM + col] = make_float2(v0 * scl, v1 * scl);
                } else {
                    if (col < DM) {
                        v0 = fmaxf(v0, 0.f) + log1pf(__expf(-fabsf(v0)));
                        v1 = fmaxf(v1, 0.f) + log1pf(__expf(-fabsf(v1)));
                        *(float2*)&g_delta[(size_t)row * DM + col] = make_float2(v0, v1);
                    } else if (col < DM + SD) {
                        *(float2*)&g_Bsel[(size_t)row * SD + col - DM] = make_float2(v0, v1);
                    } else if (col < DM + 2 * SD) {
                        *(float2*)&g_Csel[(size_t)row * SD + col - DM - SD] = make_float2(v0, v1);
                    }
                }
            }
        }
    }
}

// ---------------- fp32 -> bf16 hi/lo split --------------------------------------
__device__ __forceinline__ void split4(float4 v, uint2& hp, uint2& lp) {
    __nv_bfloat162 h01 = __floats2bfloat162_rn(v.x, v.y);
    __nv_bfloat162 h23 = __floats2bfloat162_rn(v.z, v.w);
    float lx = v.x - __bfloat162float(h01.x);
    float ly = v.y - __bfloat162float(h01.y);
    float lz = v.z - __bfloat162float(h23.x);
    float lw = v.w - __bfloat162float(h23.y);
    __nv_bfloat162 l01 = __floats2bfloat162_rn(lx, ly);
    __nv_bfloat162 l23 = __floats2bfloat162_rn(lz, lw);
    hp.x = *(uint32_t*)&h01; hp.y = *(uint32_t*)&h23;
    lp.x = *(uint32_t*)&l01; lp.y = *(uint32_t*)&l23;
}

__global__ void __launch_bounds__(256) convert_x(const float* __restrict__ x)
{
    int m = blockIdx.x, j = threadIdx.x * 4;
    float4 v = *(const float4*)&x[(size_t)m * DM + j];
    uint2 hp, lp; split4(v, hp, lp);
    *(uint2*)&g_xh[(size_t)m * DM + j] = hp;
    *(uint2*)&g_xl[(size_t)m * DM + j] = lp;
}

__global__ void __launch_bounds__(256) convert_w_all(
    const float* __restrict__ Wd, const float* __restrict__ WB,
    const float* __restrict__ WC, const float* __restrict__ Wc)
{
    int k = blockIdx.x, t = threadIdx.x;
    int j = t * 4;
    {
        float4 v = *(const float4*)&Wd[(size_t)k * DM + j];
        uint2 hp, lp; split4(v, hp, lp);
        *(uint2*)&g_w1[(size_t)k * NB1 + j]        = hp;
        *(uint2*)&g_w1[(size_t)(k + DM) * NB1 + j] = lp;
    }
    {
        float4 v = *(const float4*)&Wc[(size_t)k * DM + j];
        uint2 hp, lp; split4(v, hp, lp);
        *(uint2*)&g_w2[(size_t)k * DM + j]        = hp;
        *(uint2*)&g_w2[(size_t)(k + DM) * DM + j] = lp;
    }
    if (t < 128) {
        float bv = 0.f;
        if (t < SD) bv = WB[k * SD + t];
        else if (t < 2 * SD) bv = WC[k * SD + t - SD];
        __nv_bfloat16 h = __float2bfloat16(bv);
        __nv_bfloat16 l = __float2bfloat16(bv - __bfloat162float(h));
        g_w1[(size_t)k * NB1 + DM + t]        = h;
        g_w1[(size_t)(k + DM) * NB1 + DM + t] = l;
    }
}

// ---------------- chunked selective scan (2 states/thread, 32 d per block) --------
#define TC1 64
// pass1: chunks 0..14, both batches. Thread: d = g (tid>>3), n = {l, l+8} (l = tid&7)
__global__ void __launch_bounds__(256) scan_pass1(
    const float* __restrict__ x, const float* __restrict__ A_log)
{
    int blk  = blockIdx.x;               // 2 * 32 * 15 = 960
    int c    = blk % 15;
    int rem  = blk / 15;                 // 0..63
    int dblk = rem & 31;
    int b    = rem >> 5;
    int tid  = threadIdx.x;
    int g    = tid >> 3, l = tid & 7;
    int d0   = dblk << 5, d = d0 + g;

    __shared__ float2 s_dx[TC1][32];     // (dt, dt*x) per (t, d)
    __shared__ float2 s_bp[TC1][8];      // (B[l], B[l+8]) per t

    float a20 = -__expf(A_log[d * SD + l])     * LOG2E;
    float a21 = -__expf(A_log[d * SD + l + 8]) * LOG2E;
    float h0 = 0.f, h1 = 0.f, sdt = 0.f;

    const float* dbase = g_delta + ((size_t)b * SEQ) * DM + d0;
    const float* xbase = x       + ((size_t)b * SEQ) * DM + d0;
    const float* Bbase = g_Bsel  + ((size_t)b * SEQ) * SD;
    int tstart = c * CHL;

    for (int t0 = tstart; t0 < tstart + CHL; t0 += TC1) {
        __syncthreads();
        for (int idx = tid; idx < TC1 * 32; idx += 256) {
            int r = idx >> 5, col = idx & 31;
            float dt = dbase[(size_t)(t0 + r) * DM + col];
            float xv = xbase[(size_t)(t0 + r) * DM + col];
            s_dx[r][col] = make_float2(dt, dt * xv);
        }
        for (int idx = tid; idx < TC1 * 8; idx += 256) {
            int r = idx >> 3, ll = idx & 7;
            const float* Br = Bbase + (size_t)(t0 + r) * SD;
            s_bp[r][ll] = make_float2(Br[ll], Br[ll + 8]);
        }
        __syncthreads();
#pragma unroll 8
        for (int t = 0; t < TC1; t++) {
            float2 dx = s_dx[t][g];
            float2 bp = s_bp[t][l];
            h0 = fmaf(h0, exp2f(dx.x * a20), dx.y * bp.x);
            h1 = fmaf(h1, exp2f(dx.x * a21), dx.y * bp.y);
            sdt += dx.x;
        }
    }
    size_t ci = ((size_t)(b * NCH + c) * DM + d) * SD;
    g_hchunk[ci + l]     = h0;
    g_hchunk[ci + l + 8] = h1;
    if (l == 0) g_sumdel[(size_t)(b * NCH + c) * DM + d] = sdt;
}

// pass3: per-thread h0 recombination + re-scan, emit y
__global__ void __launch_bounds__(256) scan_pass3(
    const float* __restrict__ x, const float* __restrict__ A_log)
{
    int blk  = blockIdx.x;               // 2 * 32 * 16 = 1024
    int c    = blk & (NCH - 1);
    int dblk = (blk >> 4) & 31;
    int b    = blk >> 9;
    int tid  = threadIdx.x;
    int g    = tid >> 3, l = tid & 7;
    int d0   = dblk << 5, d = d0 + g;

    __shared__ float2 s_dx[TC1][32];
    __shared__ float4 s_bc[TC1][8];      // (B[l], C[l], B[l+8], C[l+8])
    __shared__ float  s_y [TC1][32];

    float a20 = -__expf(A_log[d * SD + l])     * LOG2E;
    float a21 = -__expf(A_log[d * SD + l + 8]) * LOG2E;

    float h0 = 0.f, h1 = 0.f;
    for (int cc = 0; cc < c; cc++) {
        float S   = g_sumdel[(size_t)(b * NCH + cc) * DM + d];
        size_t fi = ((size_t)(b * NCH + cc) * DM + d) * SD;
        h0 = fmaf(h0, exp2f(a20 * S), g_hchunk[fi + l]);
        h1 = fmaf(h1, exp2f(a21 * S), g_hchunk[fi + l + 8]);
    }

    const float* dbase = g_delta + ((size_t)b * SEQ) * DM + d0;
    const float* xbase = x       + ((size_t)b * SEQ) * DM + d0;
    const float* Bbase = g_Bsel  + ((size_t)b * SEQ) * SD;
    const float* Cbase = g_Csel  + ((size_t)b * SEQ) * SD;
    float*       ybase = g_ssm   + ((size_t)b * SEQ) * DM + d0;
    int tstart = c * CHL;

    for (int t0 = tstart; t0 < tstart + CHL; t0 += TC1) {
        __syncthreads();
        for (int idx = tid; idx < TC1 * 32; idx += 256) {
            int r = idx >> 5, col = idx & 31;
            float dt = dbase[(size_t)(t0 + r) * DM + col];
            float xv = xbase[(size_t)(t0 + r) * DM + col];
            s_dx[r][col] = make_float2(dt, dt * xv);
        }
        for (int idx = tid; idx < TC1 * 8; idx += 256) {
            int r = idx >> 3, ll = idx & 7;
            const float* Br = Bbase + (size_t)(t0 + r) * SD;
            const float* Cr = Cbase + (size_t)(t0 + r) * SD;
            s_bc[r][ll] = make_float4(Br[ll], Cr[ll], Br[ll + 8], Cr[ll + 8]);
        }
        __syncthreads();
#pragma unroll 8
        for (int t = 0; t < TC1; t++) {
            float2 dx = s_dx[t][g];
            float4 bc = s_bc[t][l];
            h0 = fmaf(h0, exp2f(dx.x * a20), dx.y * bc.x);
            h1 = fmaf(h1, exp2f(dx.x * a21), dx.y * bc.z);
            float p = fmaf(h1, bc.w, h0 * bc.y);
            p += __shfl_xor_sync(0xffffffffu, p, 4);
            p += __shfl_xor_sync(0xffffffffu, p, 2);
            p += __shfl_xor_sync(0xffffffffu, p, 1);
            if (l == 0) s_y[t][g] = p;
        }
        __syncthreads();
        for (int idx = tid; idx < TC1 * 32; idx += 256) {
            int r = idx >> 5, col = idx & 31;
            ybase[(size_t)(t0 + r) * DM + col] = s_y[r][col];
        }
    }
}

// ---------------- layernorm -> bf16 splits + h_final ------------------------------
__global__ void __launch_bounds__(256) ln_kernel(
    const float* __restrict__ gamma, const float* __restrict__ beta)
{
    int m = blockIdx.x;
    const float* row = g_ssm + (size_t)m * DM;
    int tid = threadIdx.x;
    float4 v = *(const float4*)&row[tid * 4];
    float s  = v.x + v.y + v.z + v.w;
    float ss = v.x*v.x + v.y*v.y + v.z*v.z + v.w*v.w;
#pragma unroll
    for (int o = 16; o > 0; o >>= 1) {
        s  += __shfl_xor_sync(0xffffffffu, s,  o);
        ss += __shfl_xor_sync(0xffffffffu, ss, o);
    }
    __shared__ float rs[8], rss[8];
    if ((tid & 31) == 0) { rs[tid >> 5] = s; rss[tid >> 5] = ss; }
    __syncthreads();
    s = 0.f; ss = 0.f;
#pragma unroll
    for (int i = 0; i < 8; i++) { s += rs[i]; ss += rss[i]; }
    float mu  = s * (1.0f / DM);
    float var = ss * (1.0f / DM) - mu * mu;
    float inv = rsqrtf(var + 1e-5f);
    float4 g4 = *(const float4*)&gamma[tid * 4];
    float4 b4 = *(const float4*)&beta[tid * 4];
    v.x = (v.x - mu) * inv * g4.x + b4.x;
    v.y = (v.y - mu) * inv * g4.y + b4.y;
    v.z = (v.z - mu) * inv * g4.z + b4.z;
    v.w = (v.w - mu) * inv * g4.w + b4.w;

    uint2 hp, lp; split4(v, hp, lp);
    *(uint2*)&g_sh[(size_t)m * DM + tid * 4] = hp;
    *(uint2*)&g_sl[(size_t)m * DM + tid * 4] = lp;

    if ((m & (SEQ - 1)) == SEQ - 1) {
        int b = m / SEQ;
        *(float4*)&g_hfinal[b * DM + tid * 4] = v;
    }
}

// ---------------- h_proj = h_final @ W_imp -----------------------------------------
__global__ void __launch_bounds__(256) hproj_kernel(const float* __restrict__ Wimp)
{
    int b = blockIdx.y;
    int j = blockIdx.x * 256 + threadIdx.x;
    __shared__ float hf[DM];
    for (int i = threadIdx.x; i < DM; i += 256) hf[i] = g_hfinal[b * DM + i];
    __syncthreads();
    float a0 = 0.f, a1 = 0.f, a2 = 0.f, a3 = 0.f;
#pragma unroll 4
    for (int d = 0; d < DM; d += 4) {
        a0 = fmaf(hf[d+0], Wimp[(size_t)(d+0) * DM + j], a0);
        a1 = fmaf(hf[d+1], Wimp[(size_t)(d+1) * DM + j], a1);
        a2 = fmaf(hf[d+2], Wimp[(size_t)(d+2) * DM + j], a2);
        a3 = fmaf(hf[d+3], Wimp[(size_t)(d+3) * DM + j], a3);
    }
    g_hproj[b * DM + j] = (a0 + a1) + (a2 + a3);
}

// ---------------- raw_importance -----------------------------------------------------
__global__ void __launch_bounds__(256) raw_kernel(
    const float* __restrict__ x, float* __restrict__ out_raw)
{
    int m    = (blockIdx.x * 256 + threadIdx.x) >> 5;
    int lane = threadIdx.x & 31;
    int b    = m >> 12;
    const float* xr = x + (size_t)m * DM;
    const float* hp = g_hproj + b * DM;
    float acc = 0.f;
    for (int d = lane * 4; d < DM; d += 128) {
        float4 xv = *(const float4*)&xr[d];
        float4 hv = *(const float4*)&hp[d];
        acc += xv.x*hv.x + xv.y*hv.y + xv.z*hv.z + xv.w*hv.w;
    }
#pragma unroll
    for (int o = 16; o > 0; o >>= 1) acc += __shfl_xor_sync(0xffffffffu, acc, o);
    if (lane == 0) { g_raw[m] = acc; out_raw[m] = acc; }
}

// ---------------- softmax over seq ---------------------------------------------------
__global__ void __launch_bounds__(1024) softmax_kernel(float* __restrict__ out_imp)
{
    int b   = blockIdx.x;
    int tid = threadIdx.x;
    const float* r = g_raw + (size_t)b * SEQ;
    float4 rv = *(const float4*)&r[tid * 4];
    float v0 = rv.x * 2.0f, v1 = rv.y * 2.0f, v2 = rv.z * 2.0f, v3 = rv.w * 2.0f;
    float mx = fmaxf(fmaxf(v0, v1), fmaxf(v2, v3));

    __shared__ float swarp[32];
    __shared__ float bval;
#pragma unroll
    for (int o = 16; o > 0; o >>= 1) mx = fmaxf(mx, __shfl_xor_sync(0xffffffffu, mx, o));
    if ((tid & 31) == 0) swarp[tid >> 5] = mx;
    __syncthreads();
    if (tid < 32) {
        float v = swarp[tid];
#pragma unroll
        for (int o = 16; o > 0; o >>= 1) v = fmaxf(v, __shfl_xor_sync(0xffffffffu, v, o));
        if (tid == 0) bval = v;
    }
    __syncthreads();
    float gmax = bval;
    float e0 = __expf(v0 - gmax), e1 = __expf(v1 - gmax);
    float e2 = __expf(v2 - gmax), e3 = __expf(v3 - gmax);
    float sum = e0 + e1 + e2 + e3;
#pragma unroll
    for (int o = 16; o > 0; o >>= 1) sum += __shfl_xor_sync(0xffffffffu, sum, o);
    __syncthreads();
    if ((tid & 31) == 0) swarp[tid >> 5] = sum;
    __syncthreads();
    if (tid < 32) {
        float v = swarp[tid];
#pragma unroll
        for (int o = 16; o > 0; o >>= 1) v += __shfl_xor_sync(0xffffffffu, v, o);
        if (tid == 0) bval = v;
    }
    __syncthreads();
    float inv = 1.0f / bval;
    float4 o4; o4.x = e0 * inv; o4.y = e1 * inv; o4.z = e2 * inv; o4.w = e3 * inv;
    *(float4*)&out_imp[(size_t)b * SEQ + tid * 4] = o4;
}

// ---------------- launch ---------------------------------------------------------------
extern "C" void kernel_launch(void* const* d_in, const int* in_sizes, int n_in,
                              void* d_out, int out_size)
{
    const float* x       = (const float*)d_in[0];
    const float* A_log   = (const float*)d_in[1];
    const float* W_delta = (const float*)d_in[2];
    const float* W_B     = (const float*)d_in[3];
    const float* W_C     = (const float*)d_in[4];
    const float* gamma   = (const float*)d_in[5];
    const float* beta    = (const float*)d_in[6];
    const float* W_ctx   = (const float*)d_in[7];
    const float* scale   = (const float*)d_in[8];
    const float* W_imp   = (const float*)d_in[9];

    float* out     = (float*)d_out;
    float* out_imp = out;
    float* out_ctx = out + M_ROWS;
    float* out_raw = out + M_ROWS + (size_t)M_ROWS * DM;

    __nv_bfloat16 *p_xh, *p_xl, *p_sh, *p_sl, *p_w1, *p_w2;
    cudaGetSymbolAddress((void**)&p_xh, g_xh);
    cudaGetSymbolAddress((void**)&p_xl, g_xl);
    cudaGetSymbolAddress((void**)&p_sh, g_sh);
    cudaGetSymbolAddress((void**)&p_sl, g_sl);
    cudaGetSymbolAddress((void**)&p_w1, g_w1);
    cudaGetSymbolAddress((void**)&p_w2, g_w2);

    static cudaStream_t s_aux = nullptr;
    static cudaEvent_t ev_fork1, ev_join1, ev_fork2, ev_join2;
    static bool init_done = false;
    if (!init_done) {
        cudaFuncSetAttribute(hmma_gemm<0>, cudaFuncAttributeMaxDynamicSharedMemorySize, GSMEM);
        cudaFuncSetAttribute(hmma_gemm<1>, cudaFuncAttributeMaxDynamicSharedMemorySize, GSMEM);
        cudaStreamCreateWithFlags(&s_aux, cudaStreamNonBlocking);
        cudaEventCreateWithFlags(&ev_fork1, cudaEventDisableTiming);
        cudaEventCreateWithFlags(&ev_join1, cudaEventDisableTiming);
        cudaEventCreateWithFlags(&ev_fork2, cudaEventDisableTiming);
        cudaEventCreateWithFlags(&ev_join2, cudaEventDisableTiming);
        init_done = true;
    }

    const __nv_bfloat16* p_w1l = p_w1 + (size_t)DM * NB1;
    const __nv_bfloat16* p_w2l = p_w2 + (size_t)DM * DM;

    // fork: convert_x (aux) || convert_w_all (main)
    cudaEventRecord(ev_fork1, 0);
    cudaStreamWaitEvent(s_aux, ev_fork1, 0);
    convert_x<<<M_ROWS, 256, 0, s_aux>>>(x);
    convert_w_all<<<DM, 256>>>(W_delta, W_B, W_C, W_ctx);
    cudaEventRecord(ev_join1, s_aux);
    cudaStreamWaitEvent(0, ev_join1, 0);

    // GEMM1: delta (softplus) + B_sel + C_sel
    hmma_gemm<1><<<dim3(NB1 / 128, M_ROWS / 128), 256, GSMEM>>>(
        p_xh, p_xl, p_w1, p_w1l, nullptr, nullptr, NB1);

    // scan (2 states/thread layout)
    scan_pass1<<<BATCH * 32 * (NCH - 1), 256>>>(x, A_log);
    scan_pass3<<<BATCH * 32 * NCH, 256>>>(x, A_log);

    ln_kernel<<<M_ROWS, 256>>>(gamma, beta);

    // fork: importance tail (aux) || GEMM2 (main)
    cudaEventRecord(ev_fork2, 0);
    cudaStreamWaitEvent(s_aux, ev_fork2, 0);
    hproj_kernel<<<dim3(DM / 256, BATCH), 256, 0, s_aux>>>(W_imp);
    raw_kernel<<<M_ROWS / 8, 256, 0, s_aux>>>(x, out_raw);
    softmax_kernel<<<BATCH, 1024, 0, s_aux>>>(out_imp);
    cudaEventRecord(ev_join2, s_aux);

    // GEMM2: context = ln(ssm) @ W_ctx * scale
    hmma_gemm<0><<<dim3(DM / 128, M_ROWS / 128), 256, GSMEM>>>(
        p_sh, p_sl, p_w2, p_w2l, out_ctx, scale, DM);

    cudaStreamWaitEvent(0, ev_join2, 0);
}

// round 17
// speedup vs baseline: 1.2086x; 1.0222x over previous
#include <cuda_runtime.h>
#include <cuda_bf16.h>
#include <math.h>
#include <stdint.h>

#define BATCH 2
#define SEQ 4096
#define DM 1024
#define SD 16
#define M_ROWS (BATCH*SEQ)   // 8192
#define NB1 1152             // GEMM1 N (1024 delta + 16 B + 16 C + 96 pad)
#define NCH 16
#define CHL (SEQ/NCH)        // 256
#define LOG2E 1.4426950408889634f

// ---------------- scratch (device globals) -----------------------------------
__device__ float g_delta[(size_t)M_ROWS * DM];
__device__ float g_Bsel [(size_t)M_ROWS * SD];
__device__ float g_Csel [(size_t)M_ROWS * SD];
__device__ float g_ssm  [(size_t)M_ROWS * DM];
__device__ float g_hfinal[BATCH * DM];
__device__ float g_hproj [BATCH * DM];
__device__ float g_raw  [M_ROWS];
__device__ float g_hchunk[(size_t)BATCH * NCH * DM * SD];
__device__ float g_sumdel[(size_t)BATCH * NCH * DM];
__device__ __nv_bfloat16 g_xh[(size_t)M_ROWS * DM];
__device__ __nv_bfloat16 g_xl[(size_t)M_ROWS * DM];
__device__ __nv_bfloat16 g_sh[(size_t)M_ROWS * DM];
__device__ __nv_bfloat16 g_sl[(size_t)M_ROWS * DM];
__device__ __nv_bfloat16 g_w1[(size_t)2 * DM * NB1];     // [k<1024 hi][k+1024 lo]
__device__ __nv_bfloat16 g_w2[(size_t)2 * DM * DM];      // W_ctx hi/lo

// ---------------- PTX helpers ------------------------------------------------
__device__ __forceinline__ void ldsm_x4(uint32_t r[4], uint32_t addr) {
    asm volatile("ldmatrix.sync.aligned.m8n8.x4.shared.b16 {%0,%1,%2,%3}, [%4];\n"
        : "=r"(r[0]), "=r"(r[1]), "=r"(r[2]), "=r"(r[3]) : "r"(addr));
}
__device__ __forceinline__ void ldsm_x4_t(uint32_t r[4], uint32_t addr) {
    asm volatile("ldmatrix.sync.aligned.m8n8.x4.trans.shared.b16 {%0,%1,%2,%3}, [%4];\n"
        : "=r"(r[0]), "=r"(r[1]), "=r"(r[2]), "=r"(r[3]) : "r"(addr));
}
__device__ __forceinline__ void mma_bf16(float c[4], const uint32_t a[4],
                                         uint32_t b0, uint32_t b1) {
    asm volatile("mma.sync.aligned.m16n8k16.row.col.f32.bf16.bf16.f32 "
        "{%0,%1,%2,%3}, {%4,%5,%6,%7}, {%8,%9}, {%0,%1,%2,%3};\n"
        : "+f"(c[0]), "+f"(c[1]), "+f"(c[2]), "+f"(c[3])
        : "r"(a[0]), "r"(a[1]), "r"(a[2]), "r"(a[3]), "r"(b0), "r"(b1));
}
__device__ __forceinline__ void cp16(uint32_t saddr, const void* gaddr) {
    asm volatile("cp.async.cg.shared.global [%0], [%1], 16;\n" :: "r"(saddr), "l"(gaddr));
}

// ---------------- GEMM smem layout (3-stage, 128x128 block) ---------------------
#define ASTG 10240                   // 128*40*2
#define BSTG 8704                    // 32*136*2
#define STGB (2*ASTG + 2*BSTG)       // 37888 per stage
#define GSMEM (3*STGB)               // 113664

// ---------------- dual-split bf16 HMMA GEMM (champion config) -------------------
template<int MODE>
__global__ void __launch_bounds__(256, 2) hmma_gemm(
    const __nv_bfloat16* __restrict__ Ahg, const __nv_bfloat16* __restrict__ Alg,
    const __nv_bfloat16* __restrict__ Bhg, const __nv_bfloat16* __restrict__ Blg,
    float* __restrict__ C, const float* __restrict__ scale_ptr, int N)
{
    extern __shared__ char smem[];
    uint32_t sb = (uint32_t)__cvta_generic_to_shared(smem);

    const int tid  = threadIdx.x;
    const int warp = tid >> 5, lane = tid & 31;
    const int wm = warp >> 2, wn = warp & 3;
    const int brow = blockIdx.y * 128, bcol = blockIdx.x * 128;

    float acc[4][4][4];
#pragma unroll
    for (int i = 0; i < 4; i++)
#pragma unroll
        for (int j = 0; j < 4; j++)
#pragma unroll
            for (int c = 0; c < 4; c++) acc[i][j][c] = 0.f;

    const __nv_bfloat16* Ah = Ahg + (size_t)brow * DM;
    const __nv_bfloat16* Al = Alg + (size_t)brow * DM;
    const __nv_bfloat16* Bh = Bhg + bcol;
    const __nv_bfloat16* Bl = Blg + bcol;

    const uint32_t a_base = (uint32_t)(((wm * 64 + (lane & 15)) * 40 + (lane >> 4) * 8) * 2);
    const uint32_t b_base = (uint32_t)((((lane & 15)) * 136 + wn * 32 + (lane >> 4) * 8) * 2);

    auto load_stage = [&](int s, int k0) {
        uint32_t base = sb + (uint32_t)(s * STGB);
#pragma unroll
        for (int i = 0; i < 2; i++) {
            int idx = tid + i * 256;
            int r = idx >> 2, c = (idx & 3) * 8;
            uint32_t so = (uint32_t)((r * 40 + c) * 2);
            const size_t go = (size_t)r * DM + k0 + c;
            cp16(base + so,        Ah + go);
            cp16(base + ASTG + so, Al + go);
        }
#pragma unroll
        for (int i = 0; i < 2; i++) {
            int idx = tid + i * 256;
            int r = idx >> 4, c = (idx & 15) * 8;
            uint32_t so = (uint32_t)((r * 136 + c) * 2);
            const size_t go = (size_t)(k0 + r) * N + c;
            cp16(base + 2 * ASTG + so,        Bh + go);
            cp16(base + 2 * ASTG + BSTG + so, Bl + go);
        }
    };

    load_stage(0, 0);
    asm volatile("cp.async.commit_group;\n");
    load_stage(1, 32);
    asm volatile("cp.async.commit_group;\n");

    const int NK = DM / 32;
    int s = 0;
    for (int kt = 0; kt < NK; kt++) {
        asm volatile("cp.async.wait_group 1;\n");
        __syncthreads();
        if (kt + 2 < NK) {
            int s2 = s + 2; if (s2 >= 3) s2 -= 3;
            load_stage(s2, (kt + 2) * 32);
        }
        asm volatile("cp.async.commit_group;\n");

        uint32_t stg = sb + (uint32_t)(s * STGB);
        uint32_t sAh = stg + a_base;
        uint32_t sAl = stg + ASTG + a_base;
        uint32_t sBh = stg + 2 * ASTG + b_base;
        uint32_t sBl = stg + 2 * ASTG + BSTG + b_base;
#pragma unroll
        for (int kk = 0; kk < 2; kk++) {
            const uint32_t ao = kk * 32;
            const uint32_t bo = kk * 4352;

            uint32_t ah[4][4];
#pragma unroll
            for (int mt = 0; mt < 4; mt++)
                ldsm_x4(ah[mt], sAh + ao + (uint32_t)(mt * 1280));
            uint32_t bh_[2][4];
            ldsm_x4_t(bh_[0], sBh + bo);
            ldsm_x4_t(bh_[1], sBh + bo + 32);
            uint32_t bl_[2][4];
            ldsm_x4_t(bl_[0], sBl + bo);
            ldsm_x4_t(bl_[1], sBl + bo + 32);

#pragma unroll
            for (int mt = 0; mt < 4; mt++)
#pragma unroll
                for (int nt = 0; nt < 4; nt++)
                    mma_bf16(acc[mt][nt], ah[mt],
                             bh_[nt >> 1][(nt & 1) * 2], bh_[nt >> 1][(nt & 1) * 2 + 1]);
#pragma unroll
            for (int mt = 0; mt < 4; mt++)
#pragma unroll
                for (int nt = 0; nt < 4; nt++)
                    mma_bf16(acc[mt][nt], ah[mt],
                             bl_[nt >> 1][(nt & 1) * 2], bl_[nt >> 1][(nt & 1) * 2 + 1]);

            uint32_t al[4][4];
#pragma unroll
            for (int mt = 0; mt < 4; mt++)
                ldsm_x4(al[mt], sAl + ao + (uint32_t)(mt * 1280));
#pragma unroll
            for (int mt = 0; mt < 4; mt++)
#pragma unroll
                for (int nt = 0; nt < 4; nt++)
                    mma_bf16(acc[mt][nt], al[mt],
                             bh_[nt >> 1][(nt & 1) * 2], bh_[nt >> 1][(nt & 1) * 2 + 1]);
        }
        if (++s >= 3) s -= 3;
    }

    float scl = 1.0f;
    if (MODE == 0 && scale_ptr) scl = *scale_ptr;
    const int g = lane >> 2, tg = lane & 3;
#pragma unroll
    for (int mt = 0; mt < 4; mt++) {
#pragma unroll
        for (int nt = 0; nt < 4; nt++) {
            int col = bcol + wn * 32 + nt * 8 + tg * 2;
#pragma unroll
            for (int half = 0; half < 2; half++) {
                int row = brow + wm * 64 + mt * 16 + g + half * 8;
                float v0 = acc[mt][nt][half * 2], v1 = acc[mt][nt][half * 2 + 1];
                if (MODE == 0) {
                    *(float2*)&C[(size_t)row * DM + col] = make_float2(v0 * scl, v1 * scl);
                } else {
                    if (col < DM) {
                        v0 = fmaxf(v0, 0.f) + log1pf(__expf(-fabsf(v0)));
                        v1 = fmaxf(v1, 0.f) + log1pf(__expf(-fabsf(v1)));
                        *(float2*)&g_delta[(size_t)row * DM + col] = make_float2(v0, v1);
                    } else if (col < DM + SD) {
                        *(float2*)&g_Bsel[(size_t)row * SD + col - DM] = make_float2(v0, v1);
                    } else if (col < DM + 2 * SD) {
                        *(float2*)&g_Csel[(size_t)row * SD + col - DM - SD] = make_float2(v0, v1);
                    }
                }
            }
        }
    }
}

// ---------------- fp32 -> bf16 hi/lo split --------------------------------------
__device__ __forceinline__ void split4(float4 v, uint2& hp, uint2& lp) {
    __nv_bfloat162 h01 = __floats2bfloat162_rn(v.x, v.y);
    __nv_bfloat162 h23 = __floats2bfloat162_rn(v.z, v.w);
    float lx = v.x - __bfloat162float(h01.x);
    float ly = v.y - __bfloat162float(h01.y);
    float lz = v.z - __bfloat162float(h23.x);
    float lw = v.w - __bfloat162float(h23.y);
    __nv_bfloat162 l01 = __floats2bfloat162_rn(lx, ly);
    __nv_bfloat162 l23 = __floats2bfloat162_rn(lz, lw);
    hp.x = *(uint32_t*)&h01; hp.y = *(uint32_t*)&h23;
    lp.x = *(uint32_t*)&l01; lp.y = *(uint32_t*)&l23;
}

__global__ void __launch_bounds__(256) convert_x(const float* __restrict__ x)
{
    int m = blockIdx.x, j = threadIdx.x * 4;
    float4 v = *(const float4*)&x[(size_t)m * DM + j];
    uint2 hp, lp; split4(v, hp, lp);
    *(uint2*)&g_xh[(size_t)m * DM + j] = hp;
    *(uint2*)&g_xl[(size_t)m * DM + j] = lp;
}

__global__ void __launch_bounds__(256) convert_w_all(
    const float* __restrict__ Wd, const float* __restrict__ WB,
    const float* __restrict__ WC, const float* __restrict__ Wc)
{
    int k = blockIdx.x, t = threadIdx.x;
    int j = t * 4;
    {
        float4 v = *(const float4*)&Wd[(size_t)k * DM + j];
        uint2 hp, lp; split4(v, hp, lp);
        *(uint2*)&g_w1[(size_t)k * NB1 + j]        = hp;
        *(uint2*)&g_w1[(size_t)(k + DM) * NB1 + j] = lp;
    }
    {
        float4 v = *(const float4*)&Wc[(size_t)k * DM + j];
        uint2 hp, lp; split4(v, hp, lp);
        *(uint2*)&g_w2[(size_t)k * DM + j]        = hp;
        *(uint2*)&g_w2[(size_t)(k + DM) * DM + j] = lp;
    }
    if (t < 128) {
        float bv = 0.f;
        if (t < SD) bv = WB[k * SD + t];
        else if (t < 2 * SD) bv = WC[k * SD + t - SD];
        __nv_bfloat16 h = __float2bfloat16(bv);
        __nv_bfloat16 l = __float2bfloat16(bv - __bfloat162float(h));
        g_w1[(size_t)k * NB1 + DM + t]        = h;
        g_w1[(size_t)(k + DM) * NB1 + DM + t] = l;
    }
}

// ---------------- chunked selective scan (4 states/thread, 32 d per block) --------
#define TC1 64
// Thread: d = tid>>2, states n = {l, l+4, l+8, l+12} (l = tid&3). 128 threads.
__global__ void __launch_bounds__(128) scan_pass1(
    const float* __restrict__ x, const float* __restrict__ A_log)
{
    int blk  = blockIdx.x;               // 2 * 32 * 15 = 960
    int c    = blk % 15;
    int rem  = blk / 15;
    int dblk = rem & 31;
    int b    = rem >> 5;
    int tid  = threadIdx.x;
    int g    = tid >> 2, l = tid & 3;
    int d0   = dblk << 5, d = d0 + g;

    __shared__ float2 s_dx[TC1][32];     // (dt, dt*x) per (t, d)
    __shared__ float4 s_bp[TC1][4];      // (B[l], B[l+4], B[l+8], B[l+12]) per t

    float a20 = -__expf(A_log[d * SD + l])      * LOG2E;
    float a21 = -__expf(A_log[d * SD + l + 4])  * LOG2E;
    float a22 = -__expf(A_log[d * SD + l + 8])  * LOG2E;
    float a23 = -__expf(A_log[d * SD + l + 12]) * LOG2E;
    float h0 = 0.f, h1 = 0.f, h2 = 0.f, h3 = 0.f, sdt = 0.f;

    const float* dbase = g_delta + ((size_t)b * SEQ) * DM + d0;
    const float* xbase = x       + ((size_t)b * SEQ) * DM + d0;
    const float* Bbase = g_Bsel  + ((size_t)b * SEQ) * SD;
    int tstart = c * CHL;

    for (int t0 = tstart; t0 < tstart + CHL; t0 += TC1) {
        __syncthreads();
        for (int idx = tid; idx < TC1 * 32; idx += 128) {
            int r = idx >> 5, col = idx & 31;
            float dt = dbase[(size_t)(t0 + r) * DM + col];
            float xv = xbase[(size_t)(t0 + r) * DM + col];
            s_dx[r][col] = make_float2(dt, dt * xv);
        }
        for (int idx = tid; idx < TC1 * 4; idx += 128) {
            int r = idx >> 2, ll = idx & 3;
            const float* Br = Bbase + (size_t)(t0 + r) * SD;
            s_bp[r][ll] = make_float4(Br[ll], Br[ll + 4], Br[ll + 8], Br[ll + 12]);
        }
        __syncthreads();
#pragma unroll 8
        for (int t = 0; t < TC1; t++) {
            float2 dx = s_dx[t][g];
            float4 bp = s_bp[t][l];
            h0 = fmaf(h0, exp2f(dx.x * a20), dx.y * bp.x);
            h1 = fmaf(h1, exp2f(dx.x * a21), dx.y * bp.y);
            h2 = fmaf(h2, exp2f(dx.x * a22), dx.y * bp.z);
            h3 = fmaf(h3, exp2f(dx.x * a23), dx.y * bp.w);
            sdt += dx.x;
        }
    }
    size_t ci = ((size_t)(b * NCH + c) * DM + d) * SD;
    g_hchunk[ci + l]      = h0;
    g_hchunk[ci + l + 4]  = h1;
    g_hchunk[ci + l + 8]  = h2;
    g_hchunk[ci + l + 12] = h3;
    if (l == 0) g_sumdel[(size_t)(b * NCH + c) * DM + d] = sdt;
}

// pass3: per-thread h0 recombination + re-scan, emit y
__global__ void __launch_bounds__(128) scan_pass3(
    const float* __restrict__ x, const float* __restrict__ A_log)
{
    int blk  = blockIdx.x;               // 2 * 32 * 16 = 1024
    int c    = blk & (NCH - 1);
    int dblk = (blk >> 4) & 31;
    int b    = blk >> 9;
    int tid  = threadIdx.x;
    int g    = tid >> 2, l = tid & 3;
    int d0   = dblk << 5, d = d0 + g;

    __shared__ float2 s_dx[TC1][32];
    __shared__ float4 s_b [TC1][4];      // B quads
    __shared__ float4 s_c [TC1][4];      // C quads
    __shared__ float  s_y [TC1][32];

    float a20 = -__expf(A_log[d * SD + l])      * LOG2E;
    float a21 = -__expf(A_log[d * SD + l + 4])  * LOG2E;
    float a22 = -__expf(A_log[d * SD + l + 8])  * LOG2E;
    float a23 = -__expf(A_log[d * SD + l + 12]) * LOG2E;

    float h0 = 0.f, h1 = 0.f, h2 = 0.f, h3 = 0.f;
    for (int cc = 0; cc < c; cc++) {
        float S   = g_sumdel[(size_t)(b * NCH + cc) * DM + d];
        size_t fi = ((size_t)(b * NCH + cc) * DM + d) * SD;
        h0 = fmaf(h0, exp2f(a20 * S), g_hchunk[fi + l]);
        h1 = fmaf(h1, exp2f(a21 * S), g_hchunk[fi + l + 4]);
        h2 = fmaf(h2, exp2f(a22 * S), g_hchunk[fi + l + 8]);
        h3 = fmaf(h3, exp2f(a23 * S), g_hchunk[fi + l + 12]);
    }

    const float* dbase = g_delta + ((size_t)b * SEQ) * DM + d0;
    const float* xbase = x       + ((size_t)b * SEQ) * DM + d0;
    const float* Bbase = g_Bsel  + ((size_t)b * SEQ) * SD;
    const float* Cbase = g_Csel  + ((size_t)b * SEQ) * SD;
    float*       ybase = g_ssm   + ((size_t)b * SEQ) * DM + d0;
    int tstart = c * CHL;

    for (int t0 = tstart; t0 < tstart + CHL; t0 += TC1) {
        __syncthreads();
        for (int idx = tid; idx < TC1 * 32; idx += 128) {
            int r = idx >> 5, col = idx & 31;
            float dt = dbase[(size_t)(t0 + r) * DM + col];
            float xv = xbase[(size_t)(t0 + r) * DM + col];
            s_dx[r][col] = make_float2(dt, dt * xv);
        }
        for (int idx = tid; idx < TC1 * 4; idx += 128) {
            int r = idx >> 2, ll = idx & 3;
            const float* Br = Bbase + (size_t)(t0 + r) * SD;
            const float* Cr = Cbase + (size_t)(t0 + r) * SD;
            s_b[r][ll] = make_float4(Br[ll], Br[ll + 4], Br[ll + 8], Br[ll + 12]);
            s_c[r][ll] = make_float4(Cr[ll], Cr[ll + 4], Cr[ll + 8], Cr[ll + 12]);
        }
        __syncthreads();
#pragma unroll 8
        for (int t = 0; t < TC1; t++) {
            float2 dx = s_dx[t][g];
            float4 bq = s_b[t][l];
            float4 cq = s_c[t][l];
            h0 = fmaf(h0, exp2f(dx.x * a20), dx.y * bq.x);
            h1 = fmaf(h1, exp2f(dx.x * a21), dx.y * bq.y);
            h2 = fmaf(h2, exp2f(dx.x * a22), dx.y * bq.z);
            h3 = fmaf(h3, exp2f(dx.x * a23), dx.y * bq.w);
            float p = fmaf(h3, cq.w, fmaf(h2, cq.z, fmaf(h1, cq.y, h0 * cq.x)));
            p += __shfl_xor_sync(0xffffffffu, p, 2);
            p += __shfl_xor_sync(0xffffffffu, p, 1);
            if (l == 0) s_y[t][g] = p;
        }
        __syncthreads();
        for (int idx = tid; idx < TC1 * 32; idx += 128) {
            int r = idx >> 5, col = idx & 31;
            ybase[(size_t)(t0 + r) * DM + col] = s_y[r][col];
        }
    }
}

// ---------------- layernorm -> bf16 splits + h_final ------------------------------
__global__ void __launch_bounds__(256) ln_kernel(
    const float* __restrict__ gamma, const float* __restrict__ beta)
{
    int m = blockIdx.x;
    const float* row = g_ssm + (size_t)m * DM;
    int tid = threadIdx.x;
    float4 v = *(const float4*)&row[tid * 4];
    float s  = v.x + v.y + v.z + v.w;
    float ss = v.x*v.x + v.y*v.y + v.z*v.z + v.w*v.w;
#pragma unroll
    for (int o = 16; o > 0; o >>= 1) {
        s  += __shfl_xor_sync(0xffffffffu, s,  o);
        ss += __shfl_xor_sync(0xffffffffu, ss, o);
    }
    __shared__ float rs[8], rss[8];
    if ((tid & 31) == 0) { rs[tid >> 5] = s; rss[tid >> 5] = ss; }
    __syncthreads();
    s = 0.f; ss = 0.f;
#pragma unroll
    for (int i = 0; i < 8; i++) { s += rs[i]; ss += rss[i]; }
    float mu  = s * (1.0f / DM);
    float var = ss * (1.0f / DM) - mu * mu;
    float inv = rsqrtf(var + 1e-5f);
    float4 g4 = *(const float4*)&gamma[tid * 4];
    float4 b4 = *(const float4*)&beta[tid * 4];
    v.x = (v.x - mu) * inv * g4.x + b4.x;
    v.y = (v.y - mu) * inv * g4.y + b4.y;
    v.z = (v.z - mu) * inv * g4.z + b4.z;
    v.w = (v.w - mu) * inv * g4.w + b4.w;

    uint2 hp, lp; split4(v, hp, lp);
    *(uint2*)&g_sh[(size_t)m * DM + tid * 4] = hp;
    *(uint2*)&g_sl[(size_t)m * DM + tid * 4] = lp;

    if ((m & (SEQ - 1)) == SEQ - 1) {
        int b = m / SEQ;
        *(float4*)&g_hfinal[b * DM + tid * 4] = v;
    }
}

// ---------------- h_proj = h_final @ W_imp -----------------------------------------
__global__ void __launch_bounds__(256) hproj_kernel(const float* __restrict__ Wimp)
{
    int b = blockIdx.y;
    int j = blockIdx.x * 256 + threadIdx.x;
    __shared__ float hf[DM];
    for (int i = threadIdx.x; i < DM; i += 256) hf[i] = g_hfinal[b * DM + i];
    __syncthreads();
    float a0 = 0.f, a1 = 0.f, a2 = 0.f, a3 = 0.f;
#pragma unroll 4
    for (int d = 0; d < DM; d += 4) {
        a0 = fmaf(hf[d+0], Wimp[(size_t)(d+0) * DM + j], a0);
        a1 = fmaf(hf[d+1], Wimp[(size_t)(d+1) * DM + j], a1);
        a2 = fmaf(hf[d+2], Wimp[(size_t)(d+2) * DM + j], a2);
        a3 = fmaf(hf[d+3], Wimp[(size_t)(d+3) * DM + j], a3);
    }
    g_hproj[b * DM + j] = (a0 + a1) + (a2 + a3);
}

// ---------------- raw_importance -----------------------------------------------------
__global__ void __launch_bounds__(256) raw_kernel(
    const float* __restrict__ x, float* __restrict__ out_raw)
{
    int m    = (blockIdx.x * 256 + threadIdx.x) >> 5;
    int lane = threadIdx.x & 31;
    int b    = m >> 12;
    const float* xr = x + (size_t)m * DM;
    const float* hp = g_hproj + b * DM;
    float acc = 0.f;
    for (int d = lane * 4; d < DM; d += 128) {
        float4 xv = *(const float4*)&xr[d];
        float4 hv = *(const float4*)&hp[d];
        acc += xv.x*hv.x + xv.y*hv.y + xv.z*hv.z + xv.w*hv.w;
    }
#pragma unroll
    for (int o = 16; o > 0; o >>= 1) acc += __shfl_xor_sync(0xffffffffu, acc, o);
    if (lane == 0) { g_raw[m] = acc; out_raw[m] = acc; }
}

// ---------------- softmax over seq ---------------------------------------------------
__global__ void __launch_bounds__(1024) softmax_kernel(float* __restrict__ out_imp)
{
    int b   = blockIdx.x;
    int tid = threadIdx.x;
    const float* r = g_raw + (size_t)b * SEQ;
    float4 rv = *(const float4*)&r[tid * 4];
    float v0 = rv.x * 2.0f, v1 = rv.y * 2.0f, v2 = rv.z * 2.0f, v3 = rv.w * 2.0f;
    float mx = fmaxf(fmaxf(v0, v1), fmaxf(v2, v3));

    __shared__ float swarp[32];
    __shared__ float bval;
#pragma unroll
    for (int o = 16; o > 0; o >>= 1) mx = fmaxf(mx, __shfl_xor_sync(0xffffffffu, mx, o));
    if ((tid & 31) == 0) swarp[tid >> 5] = mx;
    __syncthreads();
    if (tid < 32) {
        float v = swarp[tid];
#pragma unroll
        for (int o = 16; o > 0; o >>= 1) v = fmaxf(v, __shfl_xor_sync(0xffffffffu, v, o));
        if (tid == 0) bval = v;
    }
    __syncthreads();
    float gmax = bval;
    float e0 = __expf(v0 - gmax), e1 = __expf(v1 - gmax);
    float e2 = __expf(v2 - gmax), e3 = __expf(v3 - gmax);
    float sum = e0 + e1 + e2 + e3;
#pragma unroll
    for (int o = 16; o > 0; o >>= 1) sum += __shfl_xor_sync(0xffffffffu, sum, o);
    __syncthreads();
    if ((tid & 31) == 0) swarp[tid >> 5] = sum;
    __syncthreads();
    if (tid < 32) {
        float v = swarp[tid];
#pragma unroll
        for (int o = 16; o > 0; o >>= 1) v += __shfl_xor_sync(0xffffffffu, v, o);
        if (tid == 0) bval = v;
    }
    __syncthreads();
    float inv = 1.0f / bval;
    float4 o4; o4.x = e0 * inv; o4.y = e1 * inv; o4.z = e2 * inv; o4.w = e3 * inv;
    *(float4*)&out_imp[(size_t)b * SEQ + tid * 4] = o4;
}

// ---------------- launch ---------------------------------------------------------------
extern "C" void kernel_launch(void* const* d_in, const int* in_sizes, int n_in,
                              void* d_out, int out_size)
{
    const float* x       = (const float*)d_in[0];
    const float* A_log   = (const float*)d_in[1];
    const float* W_delta = (const float*)d_in[2];
    const float* W_B     = (const float*)d_in[3];
    const float* W_C     = (const float*)d_in[4];
    const float* gamma   = (const float*)d_in[5];
    const float* beta    = (const float*)d_in[6];
    const float* W_ctx   = (const float*)d_in[7];
    const float* scale   = (const float*)d_in[8];
    const float* W_imp   = (const float*)d_in[9];

    float* out     = (float*)d_out;
    float* out_imp = out;
    float* out_ctx = out + M_ROWS;
    float* out_raw = out + M_ROWS + (size_t)M_ROWS * DM;

    __nv_bfloat16 *p_xh, *p_xl, *p_sh, *p_sl, *p_w1, *p_w2;
    cudaGetSymbolAddress((void**)&p_xh, g_xh);
    cudaGetSymbolAddress((void**)&p_xl, g_xl);
    cudaGetSymbolAddress((void**)&p_sh, g_sh);
    cudaGetSymbolAddress((void**)&p_sl, g_sl);
    cudaGetSymbolAddress((void**)&p_w1, g_w1);
    cudaGetSymbolAddress((void**)&p_w2, g_w2);

    static cudaStream_t s_aux = nullptr;
    static cudaEvent_t ev_fork1, ev_join1, ev_fork2, ev_join2;
    static bool init_done = false;
    if (!init_done) {
        cudaFuncSetAttribute(hmma_gemm<0>, cudaFuncAttributeMaxDynamicSharedMemorySize, GSMEM);
        cudaFuncSetAttribute(hmma_gemm<1>, cudaFuncAttributeMaxDynamicSharedMemorySize, GSMEM);
        cudaStreamCreateWithFlags(&s_aux, cudaStreamNonBlocking);
        cudaEventCreateWithFlags(&ev_fork1, cudaEventDisableTiming);
        cudaEventCreateWithFlags(&ev_join1, cudaEventDisableTiming);
        cudaEventCreateWithFlags(&ev_fork2, cudaEventDisableTiming);
        cudaEventCreateWithFlags(&ev_join2, cudaEventDisableTiming);
        init_done = true;
    }

    const __nv_bfloat16* p_w1l = p_w1 + (size_t)DM * NB1;
    const __nv_bfloat16* p_w2l = p_w2 + (size_t)DM * DM;

    // fork: convert_x (aux) || convert_w_all (main)
    cudaEventRecord(ev_fork1, 0);
    cudaStreamWaitEvent(s_aux, ev_fork1, 0);
    convert_x<<<M_ROWS, 256, 0, s_aux>>>(x);
    convert_w_all<<<DM, 256>>>(W_delta, W_B, W_C, W_ctx);
    cudaEventRecord(ev_join1, s_aux);
    cudaStreamWaitEvent(0, ev_join1, 0);

    // GEMM1: delta (softplus) + B_sel + C_sel
    hmma_gemm<1><<<dim3(NB1 / 128, M_ROWS / 128), 256, GSMEM>>>(
        p_xh, p_xl, p_w1, p_w1l, nullptr, nullptr, NB1);

    // scan (4 states/thread layout)
    scan_pass1<<<BATCH * 32 * (NCH - 1), 128>>>(x, A_log);
    scan_pass3<<<BATCH * 32 * NCH, 128>>>(x, A_log);

    ln_kernel<<<M_ROWS, 256>>>(gamma, beta);

    // fork: importance tail (aux) || GEMM2 (main)
    cudaEventRecord(ev_fork2, 0);
    cudaStreamWaitEvent(s_aux, ev_fork2, 0);
    hproj_kernel<<<dim3(DM / 256, BATCH), 256, 0, s_aux>>>(W_imp);
    raw_kernel<<<M_ROWS / 8, 256, 0, s_aux>>>(x, out_raw);
    softmax_kernel<<<BATCH, 1024, 0, s_aux>>>(out_imp);
    cudaEventRecord(ev_join2, s_aux);

    // GEMM2: context = ln(ssm) @ W_ctx * scale
    hmma_gemm<0><<<dim3(DM / 128, M_ROWS / 128), 256, GSMEM>>>(
        p_sh, p_sl, p_w2, p_w2l, out_ctx, scale, DM);

    cudaStreamWaitEvent(0, ev_join2, 0);
}